// round 4
// baseline (speedup 1.0000x reference)
#include <cuda_runtime.h>
#include <cuda_bf16.h>
#include <math.h>
#include <stdint.h>

// Problem constants
#define B_SZ   4096
#define N_AG   11
#define L_T    12
#define D_DIM  256
#define BN_ROWS (B_SZ * N_AG)      // 45056
#define MTILES  (BN_ROWS / 128)    // 352

// ---------------- device scratch ----------------
__device__ float g_M4[4 * 256];
__device__ float g_biasT[12 * 256];
__device__ float g_Weff[48 * 256];
__device__ float g_ceffp[12 * 256];
__device__ float g_ceff[256];
__device__ float g_G[48 * 256];
__device__ float g_cb[11 * 256];
__device__ float g_msgin[(size_t)BN_ROWS * 512];  // [ftraj | agg]
__device__ float g_hypin[(size_t)BN_ROWS * 512];  // [ftraj | hag]
__device__ float g_inter[(size_t)BN_ROWS * 256];  // ftraj_inter
__device__ float g_feat [(size_t)BN_ROWS * 64];   // feat_bs
__device__ float g_hyp  [(size_t)BN_ROWS * 256];  // relu(hypin@W_hyp+b)
__device__ float g_h    [(size_t)BN_ROWS * 128];  // relu(final@W_out+b)
__device__ float g_zero64[64];                    // zero bias (never written)

// split-transposed weights: Wt[n][seg*K + k]; seg0=hi, seg1=lo, seg2=hi
__device__ __nv_bfloat16 g_Wmsg_t[256 * 1536];
__device__ __nv_bfloat16 g_Whyp_t[256 * 1536];
__device__ __nv_bfloat16 g_Wout_t[128 * 4608];
__device__ __nv_bfloat16 g_Wline_t[64 * 768];
__device__ __nv_bfloat16 g_Wqz_t [64 * 384];

// ---------------- helpers ----------------
#define SWZ(o) ((o) ^ (((o) >> 3) & 0x70))
__device__ __forceinline__ uint32_t smem_u32(const void* p) {
    uint32_t a;
    asm("{ .reg .u64 t; cvta.to.shared.u64 t, %1; cvt.u32.u64 %0, t; }" : "=r"(a) : "l"(p));
    return a;
}
__device__ __forceinline__ void ldm_x4(uint32_t* r, uint32_t addr) {
    asm volatile("ldmatrix.sync.aligned.m8n8.x4.shared.b16 {%0,%1,%2,%3}, [%4];"
                 : "=r"(r[0]), "=r"(r[1]), "=r"(r[2]), "=r"(r[3]) : "r"(addr));
}
__device__ __forceinline__ void mma16816(float* c, const uint32_t* a, const uint32_t* b) {
    asm("mma.sync.aligned.m16n8k16.row.col.f32.bf16.bf16.f32 "
        "{%0,%1,%2,%3},{%4,%5,%6,%7},{%8,%9},{%0,%1,%2,%3};"
        : "+f"(c[0]), "+f"(c[1]), "+f"(c[2]), "+f"(c[3])
        : "r"(a[0]), "r"(a[1]), "r"(a[2]), "r"(a[3]), "r"(b[0]), "r"(b[1]));
}

// ---------------- precompute kernels ----------------
__global__ void pk1(const float* __restrict__ W_in, const float* __restrict__ b_in,
                    const float* __restrict__ W_pos, const float* __restrict__ b_pos) {
    __shared__ float pe[12 * 256];
    const int tid = threadIdx.x;
    for (int idx = tid; idx < 12 * 256; idx += 256) {
        int t = idx >> 8, k = idx & 255;
        int i2 = k & ~1;
        float div = expf(-logf(10000.0f) * (float)i2 / 256.0f);
        float arg = (float)t * div;
        pe[idx] = (k & 1) ? cosf(arg) : sinf(arg);
    }
    __syncthreads();
    const int d = tid;
    float m[4] = {0.f, 0.f, 0.f, 0.f};
    float bb = 0.f;
    for (int k = 0; k < 256; k++) {
        float w = W_pos[k * 256 + d];
        #pragma unroll
        for (int r = 0; r < 4; r++) m[r] += W_in[r * 256 + k] * w;
        bb += b_in[k] * w;
    }
    #pragma unroll
    for (int r = 0; r < 4; r++) g_M4[r * 256 + d] = m[r];
    float acc[12];
    #pragma unroll
    for (int t = 0; t < 12; t++) acc[t] = bb + b_pos[d];
    for (int k = 0; k < 256; k++) {
        float w = W_pos[(256 + k) * 256 + d];
        #pragma unroll
        for (int t = 0; t < 12; t++) acc[t] += pe[t * 256 + k] * w;
    }
    #pragma unroll
    for (int t = 0; t < 12; t++) g_biasT[t * 256 + d] = acc[t];
}

__global__ void pk2(const float* __restrict__ W_fc2) {
    const int t = blockIdx.x, d = threadIdx.x;
    float accW[4] = {0.f, 0.f, 0.f, 0.f};
    float accC = 0.f;
    #pragma unroll 4
    for (int m = 0; m < 256; m++) {
        float w = W_fc2[(size_t)((t << 8) + m) * 256 + d];
        float bt = g_biasT[(t << 8) + m];
        #pragma unroll
        for (int r = 0; r < 4; r++) accW[r] += g_M4[r * 256 + m] * w;
        accC += bt * w;
    }
    #pragma unroll
    for (int r = 0; r < 4; r++) g_Weff[(t * 4 + r) * 256 + d] = accW[r];
    g_ceffp[t * 256 + d] = accC;
}

__global__ void pk3a(const float* __restrict__ b_fc2) {
    const int m = threadIdx.x;
    float s = b_fc2[m];
    #pragma unroll
    for (int t = 0; t < 12; t++) s += g_ceffp[t * 256 + m];
    g_ceff[m] = s;
}

__global__ void pk3b(const float* __restrict__ W_fc3, const float* __restrict__ b_fc3) {
    const int d = threadIdx.x;
    if (blockIdx.x < 48) {
        const int i = blockIdx.x;
        float a0 = 0.f, a1 = 0.f, a2 = 0.f, a3 = 0.f;
        #pragma unroll 4
        for (int m = 0; m < 256; m += 4) {
            a0 += g_Weff[i * 256 + m + 0] * W_fc3[(m + 0) * 256 + d];
            a1 += g_Weff[i * 256 + m + 1] * W_fc3[(m + 1) * 256 + d];
            a2 += g_Weff[i * 256 + m + 2] * W_fc3[(m + 2) * 256 + d];
            a3 += g_Weff[i * 256 + m + 3] * W_fc3[(m + 3) * 256 + d];
        }
        g_G[i * 256 + d] = (a0 + a1) + (a2 + a3);
    } else {
        float a0 = b_fc3[d], a1 = 0.f, a2 = 0.f, a3 = 0.f;
        #pragma unroll 4
        for (int m = 0; m < 256; m += 4) {
            a0 += g_ceff[m + 0] * W_fc3[(m + 0) * 256 + d];
            a1 += g_ceff[m + 1] * W_fc3[(m + 1) * 256 + d];
            a2 += g_ceff[m + 2] * W_fc3[(m + 2) * 256 + d];
            a3 += g_ceff[m + 3] * W_fc3[(m + 3) * 256 + d];
        }
        float acc = (a0 + a1) + (a2 + a3);
        #pragma unroll
        for (int n = 0; n < 11; n++) g_cb[n * 256 + d] = acc + W_fc3[(256 + n) * 256 + d];
    }
}

// build split-transposed weights: Wt[n][seg*K + k] = (seg==1) ? lo : hi of W[k][n]
__global__ void wt_build(const float* __restrict__ W, __nv_bfloat16* __restrict__ Wt,
                         int K, int N) {
    int idx = blockIdx.x * 256 + threadIdx.x;
    int K3 = 3 * K;
    if (idx >= N * K3) return;
    int n = idx / K3, kk = idx % K3;
    int seg = kk / K, k = kk % K;
    float w = W[(size_t)k * N + n];
    __nv_bfloat16 hi = __float2bfloat16(w);
    Wt[idx] = (seg == 1) ? __float2bfloat16(w - __bfloat162float(hi)) : hi;
}

// ---------------- per-scene kernel ----------------
__global__ void __launch_bounds__(256)
scene_kernel(const float* __restrict__ inputs) {
    __shared__ float in_s[11 * 48];
    __shared__ float ft[11 * 256];
    __shared__ float dot_s[121];
    __shared__ float corr_s[121];
    __shared__ float attn_s[121];
    __shared__ float arow_s[121];
    __shared__ float nrm[11];
    __shared__ float thr_s;

    const int b = blockIdx.x, tid = threadIdx.x;
    const float* ip = inputs + (size_t)b * 11 * 48;
    for (int i = tid; i < 528; i += 256) in_s[i] = ip[i];
    __syncthreads();

    float acc[11];
    #pragma unroll
    for (int n = 0; n < 11; n++) acc[n] = g_cb[n * 256 + tid];
    for (int k = 0; k < 48; k++) {
        float g = g_G[k * 256 + tid];
        #pragma unroll
        for (int n = 0; n < 11; n++) acc[n] += in_s[n * 48 + k] * g;
    }
    const size_t rowbase = (size_t)b * 11;
    #pragma unroll
    for (int n = 0; n < 11; n++) {
        ft[n * 256 + tid] = acc[n];
        g_msgin[(rowbase + n) * 512 + tid] = acc[n];
        g_hypin[(rowbase + n) * 512 + tid] = acc[n];
    }
    __syncthreads();

    const int warp = tid >> 5, lane = tid & 31;
    for (int p = warp; p < 121; p += 8) {
        int n = p / 11, m = p % 11;
        if (m < n) continue;
        float s = 0.f;
        #pragma unroll
        for (int i = 0; i < 8; i++)
            s += ft[n * 256 + lane + 32 * i] * ft[m * 256 + lane + 32 * i];
        #pragma unroll
        for (int o = 16; o > 0; o >>= 1) s += __shfl_down_sync(0xffffffffu, s, o);
        if (lane == 0) { dot_s[n * 11 + m] = s; dot_s[m * 11 + n] = s; }
    }
    __syncthreads();
    if (tid < 11) nrm[tid] = sqrtf(dot_s[tid * 11 + tid]);
    __syncthreads();
    if (tid < 121) {
        int n = tid / 11, m = tid % 11;
        corr_s[tid] = dot_s[tid] / (nrm[n] * nrm[m]);
    }
    __syncthreads();
    if (tid == 0) {
        float a = corr_s[0];
        for (int i = 1; i < 121; i++) a = fminf(a, corr_s[i]);
        float thr;
        if (a < 0.4f)                  thr = 0.4f;
        else if (a > 0.4f && a < 0.6f) thr = a + 0.1f;
        else                           thr = a + 0.03f;
        thr_s = thr;
    }
    __syncthreads();
    if (tid < 11) {
        const int n = tid;
        const float thr = thr_s;
        float rs = 0.f;
        #pragma unroll
        for (int m = 0; m < 11; m++) rs += (corr_s[n * 11 + m] >= thr) ? 1.0f : 0.0f;
        const float inv = 1.0f / fmaxf(rs, 1.0f);
        #pragma unroll
        for (int m = 0; m < 11; m++)
            arow_s[n * 11 + m] = (corr_s[n * 11 + m] >= thr) ? inv : 0.0f;
        const float sc = 0.0625f;
        float mx = -1e30f;
        #pragma unroll
        for (int m = 0; m < 11; m++) mx = fmaxf(mx, dot_s[n * 11 + m] * sc);
        float e[11], se = 0.f;
        #pragma unroll
        for (int m = 0; m < 11; m++) { e[m] = expf(dot_s[n * 11 + m] * sc - mx); se += e[m]; }
        const float is = 1.0f / se;
        #pragma unroll
        for (int m = 0; m < 11; m++) attn_s[n * 11 + m] = e[m] * is;
    }
    __syncthreads();
    #pragma unroll
    for (int n = 0; n < 11; n++) {
        float a = 0.f, h = 0.f;
        #pragma unroll
        for (int m = 0; m < 11; m++) {
            float f = ft[m * 256 + tid];
            a += attn_s[n * 11 + m] * f;
            h += arow_s[n * 11 + m] * f;
        }
        g_msgin[(rowbase + n) * 512 + 256 + tid] = a;
        g_hypin[(rowbase + n) * 512 + 256 + tid] = h;
    }
}

// ---------------- tensor-core GEMM via mma.sync (bf16 hi/lo 3-term split) ----------------
// D[128, NTILE] per CTA; K' = 3K segmented A' = [hi|hi|lo], Bt prebuilt [N, 3K].
// 8 warps: 4 (m) x 2 (n); warp tile 32 x NTILE/2; mma m16n8k16.
template<int NTILE>
__global__ void __launch_bounds__(256, 1)
k_mma(const float* __restrict__ A, const float* __restrict__ past,
      const __nv_bfloat16* __restrict__ Bt, const float* __restrict__ bias,
      float* __restrict__ out, int K, int N, int mode, int relu) {
    constexpr int NF = NTILE / 16;       // n-frags per warp
    constexpr int BV = NTILE / 32;       // uint4 B loads per thread per chunk
    constexpr int BB = NTILE * 128;      // bytes per B buffer
    extern __shared__ char smx[];
    const uint32_t sb = smem_u32(smx);

    const int tid = threadIdx.x;
    const int lane = tid & 31, wid = tid >> 5;
    const int wm = wid >> 1, wn = wid & 1;
    const int m0 = blockIdx.y * 128;
    const int n0 = blockIdx.x * NTILE;
    const int K3 = 3 * K;
    const int NIT = K3 / 64;

    // staging coords: each thread owns half a row of the 128x64 A chunk
    const int row = tid >> 1, half = tid & 1;

    // ldmatrix lane->address components
    const int t4 = lane >> 3;
    const int aRow = (lane & 7) + (t4 & 1) * 8;       // + mi*16 + wm*32
    const int aK8  = (t4 >> 1) * 8;                   // + k16*16
    const int bNl  = (t4 >> 1) * 8 + (lane & 7);      // + fp*16 + wn*NTILE/2
    const int bK8  = (t4 & 1) * 8;

    float4 af[8];
    uint4  bfr[BV];

    auto loadA = [&](int it) {
        const int kk = it * 64, seg = kk / K;
        const int ksrc = kk - seg * K + half * 32;
        const float* p;
        if (mode == 0) {
            p = A + (size_t)(m0 + row) * K + ksrc;
        } else {
            size_t r = (size_t)(m0 + row);
            if (ksrc < 960)       p = past    + r * 960 + ksrc;
            else if (ksrc < 1216) p = g_msgin + r * 512 + (ksrc - 960);
            else if (ksrc < 1472) p = g_inter + r * 256 + (ksrc - 1216);
            else                  p = g_feat  + r * 64  + (ksrc - 1472);
        }
        const float4* p4 = (const float4*)p;
        #pragma unroll
        for (int g = 0; g < 8; g++) af[g] = p4[g];
    };
    auto loadB = [&](int it) {
        const int kk = it * 64;
        #pragma unroll
        for (int v = 0; v < BV; v++) {
            int idx = tid + v * 256;
            int rr = idx >> 3, g = idx & 7;
            bfr[v] = *(const uint4*)(Bt + (size_t)(n0 + rr) * K3 + kk + g * 8);
        }
    };
    auto storeAB = [&](int it) {
        const int seg = (it * 64) / K;
        const int buf = it & 1;
        char* As = smx + buf * 16384;
        #pragma unroll
        for (int g = 0; g < 8; g++) {
            float f0 = af[g].x, f1 = af[g].y, f2 = af[g].z, f3 = af[g].w;
            __nv_bfloat162 h01, h23;
            if (seg < 2) {
                h01 = __float22bfloat162_rn(make_float2(f0, f1));
                h23 = __float22bfloat162_rn(make_float2(f2, f3));
            } else {
                __nv_bfloat16 e0 = __float2bfloat16(f0), e1 = __float2bfloat16(f1);
                __nv_bfloat16 e2 = __float2bfloat16(f2), e3 = __float2bfloat16(f3);
                h01 = __float22bfloat162_rn(make_float2(f0 - __bfloat162float(e0),
                                                        f1 - __bfloat162float(e1)));
                h23 = __float22bfloat162_rn(make_float2(f2 - __bfloat162float(e2),
                                                        f3 - __bfloat162float(e3)));
            }
            uint2 pkd;
            pkd.x = *(uint32_t*)&h01;
            pkd.y = *(uint32_t*)&h23;
            uint32_t off = (uint32_t)(row * 128 + half * 64 + g * 8);
            *(uint2*)(As + SWZ(off)) = pkd;
        }
        char* Bs = smx + 32768 + buf * BB;
        #pragma unroll
        for (int v = 0; v < BV; v++) {
            int idx = tid + v * 256;
            int rr = idx >> 3, g = idx & 7;
            uint32_t off = (uint32_t)(rr * 128 + g * 16);
            *(uint4*)(Bs + SWZ(off)) = bfr[v];
        }
    };

    float c[2][NF][4];
    #pragma unroll
    for (int mi = 0; mi < 2; mi++)
        #pragma unroll
        for (int f = 0; f < NF; f++)
            #pragma unroll
            for (int q = 0; q < 4; q++) c[mi][f][q] = 0.f;

    loadA(0); loadB(0); storeAB(0);
    __syncthreads();

    for (int it = 0; it < NIT; it++) {
        const int buf = it & 1;
        if (it + 1 < NIT) { loadA(it + 1); loadB(it + 1); }

        const uint32_t sa = sb + buf * 16384;
        const uint32_t sbb = sb + 32768 + buf * BB;
        #pragma unroll
        for (int k16 = 0; k16 < 4; k16++) {
            uint32_t a[2][4], bfrag[NF][2];
            #pragma unroll
            for (int mi = 0; mi < 2; mi++) {
                uint32_t off = (uint32_t)((wm * 32 + mi * 16 + aRow) * 128
                                          + (k16 * 16 + aK8) * 2);
                ldm_x4(a[mi], sa + SWZ(off));
            }
            #pragma unroll
            for (int fp = 0; fp < NF / 2; fp++) {
                uint32_t r4[4];
                uint32_t off = (uint32_t)((wn * (NTILE / 2) + fp * 16 + bNl) * 128
                                          + (k16 * 16 + bK8) * 2);
                ldm_x4(r4, sbb + SWZ(off));
                bfrag[2 * fp][0] = r4[0]; bfrag[2 * fp][1] = r4[1];
                bfrag[2 * fp + 1][0] = r4[2]; bfrag[2 * fp + 1][1] = r4[3];
            }
            #pragma unroll
            for (int mi = 0; mi < 2; mi++)
                #pragma unroll
                for (int f = 0; f < NF; f++)
                    mma16816(c[mi][f], a[mi], bfrag[f]);
        }
        if (it + 1 < NIT) storeAB(it + 1);
        __syncthreads();
    }

    // epilogue
    const int groupID = lane >> 2, tig = lane & 3;
    #pragma unroll
    for (int mi = 0; mi < 2; mi++) {
        const int r0 = m0 + wm * 32 + mi * 16 + groupID;
        #pragma unroll
        for (int f = 0; f < NF; f++) {
            const int col = n0 + wn * (NTILE / 2) + f * 8 + tig * 2;
            float b0 = bias[col], b1 = bias[col + 1];
            float2 v0 = make_float2(c[mi][f][0] + b0, c[mi][f][1] + b1);
            float2 v1 = make_float2(c[mi][f][2] + b0, c[mi][f][3] + b1);
            if (relu) {
                v0.x = fmaxf(v0.x, 0.f); v0.y = fmaxf(v0.y, 0.f);
                v1.x = fmaxf(v1.x, 0.f); v1.y = fmaxf(v1.y, 0.f);
            }
            *(float2*)(out + (size_t)r0 * N + col) = v0;
            *(float2*)(out + (size_t)(r0 + 8) * N + col) = v1;
        }
    }
}

// ---------------- launch ----------------
extern "C" void kernel_launch(void* const* d_in, const int* in_sizes, int n_in,
                              void* d_out, int out_size) {
    const float* inputs = (const float*)d_in[0];
    const float* past   = (const float*)d_in[1];
    const float* W_in   = (const float*)d_in[2];
    const float* b_in   = (const float*)d_in[3];
    const float* W_pos  = (const float*)d_in[4];
    const float* b_pos  = (const float*)d_in[5];
    const float* W_fc2  = (const float*)d_in[6];
    const float* b_fc2  = (const float*)d_in[7];
    const float* W_fc3  = (const float*)d_in[8];
    const float* b_fc3  = (const float*)d_in[9];
    const float* W_msg  = (const float*)d_in[10];
    const float* b_msg  = (const float*)d_in[11];
    const float* W_hyp  = (const float*)d_in[12];
    const float* b_hyp  = (const float*)d_in[13];
    const float* W_line = (const float*)d_in[14];
    const float* W_out  = (const float*)d_in[15];
    const float* b_out  = (const float*)d_in[16];
    const float* W_qz   = (const float*)d_in[17];
    const float* b_qz   = (const float*)d_in[18];
    float* out = (float*)d_out;

    static int s_init = 0;
    static void *pWmsg, *pWhyp, *pWout, *pWline, *pWqz;
    static void *pMsgin, *pHypin, *pInter, *pFeat, *pHyp, *pH, *pZero;
    if (!s_init) {
        cudaGetSymbolAddress(&pWmsg,  g_Wmsg_t);
        cudaGetSymbolAddress(&pWhyp,  g_Whyp_t);
        cudaGetSymbolAddress(&pWout,  g_Wout_t);
        cudaGetSymbolAddress(&pWline, g_Wline_t);
        cudaGetSymbolAddress(&pWqz,   g_Wqz_t);
        cudaGetSymbolAddress(&pMsgin, g_msgin);
        cudaGetSymbolAddress(&pHypin, g_hypin);
        cudaGetSymbolAddress(&pInter, g_inter);
        cudaGetSymbolAddress(&pFeat,  g_feat);
        cudaGetSymbolAddress(&pHyp,   g_hyp);
        cudaGetSymbolAddress(&pH,     g_h);
        cudaGetSymbolAddress(&pZero,  g_zero64);
        cudaFuncSetAttribute(k_mma<128>, cudaFuncAttributeMaxDynamicSharedMemorySize, 65536);
        cudaFuncSetAttribute(k_mma<64>,  cudaFuncAttributeMaxDynamicSharedMemorySize, 49152);
        s_init = 1;
    }

    pk1<<<1, 256>>>(W_in, b_in, W_pos, b_pos);
    pk2<<<12, 256>>>(W_fc2);
    pk3a<<<1, 256>>>(b_fc2);
    pk3b<<<49, 256>>>(W_fc3, b_fc3);
    wt_build<<<(256 * 1536 + 255) / 256, 256>>>(W_msg,  (__nv_bfloat16*)pWmsg,  512, 256);
    wt_build<<<(256 * 1536 + 255) / 256, 256>>>(W_hyp,  (__nv_bfloat16*)pWhyp,  512, 256);
    wt_build<<<(128 * 4608 + 255) / 256, 256>>>(W_out,  (__nv_bfloat16*)pWout,  1536, 128);
    wt_build<<<(64 * 768 + 255) / 256, 256>>>(W_line, (__nv_bfloat16*)pWline, 256, 64);
    wt_build<<<(64 * 384 + 255) / 256, 256>>>(W_qz,   (__nv_bfloat16*)pWqz,   128, 64);
    scene_kernel<<<B_SZ, 256>>>(inputs);

    // inter = relu(msgin @ W_msg + b_msg)   [45056,512] -> [45056,256]
    k_mma<128><<<dim3(2, MTILES), 256, 65536>>>((const float*)pMsgin, nullptr,
        (const __nv_bfloat16*)pWmsg, b_msg, (float*)pInter, 512, 256, 0, 1);
    // hyp = relu(hypin @ W_hyp + b_hyp)
    k_mma<128><<<dim3(2, MTILES), 256, 65536>>>((const float*)pHypin, nullptr,
        (const __nv_bfloat16*)pWhyp, b_hyp, (float*)pHyp, 512, 256, 0, 1);
    // feat = hyp @ W_line                   [45056,256] -> [45056,64]
    k_mma<64><<<dim3(1, MTILES), 256, 49152>>>((const float*)pHyp, nullptr,
        (const __nv_bfloat16*)pWline, (const float*)pZero, (float*)pFeat, 256, 64, 0, 0);
    // h = relu([past|ftraj|inter|feat] @ W_out + b_out)   K=1536 -> 128
    k_mma<128><<<dim3(1, MTILES), 256, 65536>>>(nullptr, past,
        (const __nv_bfloat16*)pWout, b_out, (float*)pH, 1536, 128, 1, 1);
    // out = h @ W_qz + b_qz                 [45056,128] -> [45056,64]
    k_mma<64><<<dim3(1, MTILES), 256, 49152>>>((const float*)pH, nullptr,
        (const __nv_bfloat16*)pWqz, b_qz, out, 128, 64, 0, 0);
}

// round 5
// speedup vs baseline: 1.9190x; 1.9190x over previous
#include <cuda_runtime.h>
#include <cuda_bf16.h>
#include <math.h>
#include <stdint.h>

// Problem constants
#define B_SZ   4096
#define N_AG   11
#define BN_ROWS (B_SZ * N_AG)      // 45056
#define MTILES  (BN_ROWS / 128)    // 352

// ---------------- device scratch ----------------
__device__ float g_M4[4 * 256];
__device__ float g_biasT[12 * 256];
__device__ float g_Weff[48 * 256];
__device__ float g_ceffp[12 * 256];
__device__ float g_ceff[256];
__device__ float g_G[48 * 256];
__device__ float g_cb[11 * 256];
__device__ float g_zero64[64];

// bf16 hi/lo activations
__device__ __nv_bfloat16 g_past_hi[(size_t)BN_ROWS * 960];
__device__ __nv_bfloat16 g_past_lo[(size_t)BN_ROWS * 960];
__device__ __nv_bfloat16 g_msg_hi [(size_t)BN_ROWS * 512];
__device__ __nv_bfloat16 g_msg_lo [(size_t)BN_ROWS * 512];
__device__ __nv_bfloat16 g_hpi_hi [(size_t)BN_ROWS * 512];
__device__ __nv_bfloat16 g_hpi_lo [(size_t)BN_ROWS * 512];
__device__ __nv_bfloat16 g_int_hi [(size_t)BN_ROWS * 256];
__device__ __nv_bfloat16 g_int_lo [(size_t)BN_ROWS * 256];
__device__ __nv_bfloat16 g_hyp_hi [(size_t)BN_ROWS * 256];
__device__ __nv_bfloat16 g_hyp_lo [(size_t)BN_ROWS * 256];
__device__ __nv_bfloat16 g_fea_hi [(size_t)BN_ROWS * 64];
__device__ __nv_bfloat16 g_fea_lo [(size_t)BN_ROWS * 64];
// transposed split weights: [n][K]
__device__ __nv_bfloat16 g_Wmsg_hi[256 * 512],  g_Wmsg_lo[256 * 512];
__device__ __nv_bfloat16 g_Whyp_hi[256 * 512],  g_Whyp_lo[256 * 512];
__device__ __nv_bfloat16 g_Wout_hi[128 * 1536], g_Wout_lo[128 * 1536];
__device__ __nv_bfloat16 g_Wlin_hi[64 * 256],   g_Wlin_lo[64 * 256];
__device__ __nv_bfloat16 g_Wqz_hi [64 * 128],   g_Wqz_lo [64 * 128];

// ---------------- helpers ----------------
#define SWZ(o) ((o) ^ (((o) >> 3) & 0x70))
__device__ __forceinline__ uint32_t smem_u32(const void* p) {
    uint32_t a;
    asm("{ .reg .u64 t; cvta.to.shared.u64 t, %1; cvt.u32.u64 %0, t; }" : "=r"(a) : "l"(p));
    return a;
}
__device__ __forceinline__ void ldm_x4(uint32_t* r, uint32_t addr) {
    asm volatile("ldmatrix.sync.aligned.m8n8.x4.shared.b16 {%0,%1,%2,%3}, [%4];"
                 : "=r"(r[0]), "=r"(r[1]), "=r"(r[2]), "=r"(r[3]) : "r"(addr));
}
__device__ __forceinline__ void mma16816(float* c, const uint32_t* a, const uint32_t* b) {
    asm("mma.sync.aligned.m16n8k16.row.col.f32.bf16.bf16.f32 "
        "{%0,%1,%2,%3},{%4,%5,%6,%7},{%8,%9},{%0,%1,%2,%3};"
        : "+f"(c[0]), "+f"(c[1]), "+f"(c[2]), "+f"(c[3])
        : "r"(a[0]), "r"(a[1]), "r"(a[2]), "r"(a[3]), "r"(b[0]), "r"(b[1]));
}
__device__ __forceinline__ void cp16(uint32_t dst, const void* src) {
    asm volatile("cp.async.cg.shared.global [%0], [%1], 16;"
                 :: "r"(dst), "l"(__cvta_generic_to_global(src)) : "memory");
}
#define CP_COMMIT() asm volatile("cp.async.commit_group;" ::: "memory")
#define CP_WAIT(n)  asm volatile("cp.async.wait_group %0;" :: "n"(n) : "memory")
__device__ __forceinline__ void split2(float x, __nv_bfloat16& h, __nv_bfloat16& l) {
    h = __float2bfloat16(x);
    l = __float2bfloat16(x - __bfloat162float(h));
}

// ---------------- precompute kernels ----------------
__global__ void pk1(const float* __restrict__ W_in, const float* __restrict__ b_in,
                    const float* __restrict__ W_pos, const float* __restrict__ b_pos) {
    __shared__ float pe[12 * 256];
    const int tid = threadIdx.x;
    for (int idx = tid; idx < 12 * 256; idx += 256) {
        int t = idx >> 8, k = idx & 255;
        int i2 = k & ~1;
        float div = expf(-logf(10000.0f) * (float)i2 / 256.0f);
        float arg = (float)t * div;
        pe[idx] = (k & 1) ? cosf(arg) : sinf(arg);
    }
    __syncthreads();
    const int d = tid;
    float m[4] = {0.f, 0.f, 0.f, 0.f};
    float bb = 0.f;
    for (int k = 0; k < 256; k++) {
        float w = W_pos[k * 256 + d];
        #pragma unroll
        for (int r = 0; r < 4; r++) m[r] += W_in[r * 256 + k] * w;
        bb += b_in[k] * w;
    }
    #pragma unroll
    for (int r = 0; r < 4; r++) g_M4[r * 256 + d] = m[r];
    float acc[12];
    #pragma unroll
    for (int t = 0; t < 12; t++) acc[t] = bb + b_pos[d];
    for (int k = 0; k < 256; k++) {
        float w = W_pos[(256 + k) * 256 + d];
        #pragma unroll
        for (int t = 0; t < 12; t++) acc[t] += pe[t * 256 + k] * w;
    }
    #pragma unroll
    for (int t = 0; t < 12; t++) g_biasT[t * 256 + d] = acc[t];
}

__global__ void pk2(const float* __restrict__ W_fc2) {
    const int t = blockIdx.x, d = threadIdx.x;
    float accW[4] = {0.f, 0.f, 0.f, 0.f};
    float accC = 0.f;
    #pragma unroll 4
    for (int m = 0; m < 256; m++) {
        float w = W_fc2[(size_t)((t << 8) + m) * 256 + d];
        float bt = g_biasT[(t << 8) + m];
        #pragma unroll
        for (int r = 0; r < 4; r++) accW[r] += g_M4[r * 256 + m] * w;
        accC += bt * w;
    }
    #pragma unroll
    for (int r = 0; r < 4; r++) g_Weff[(t * 4 + r) * 256 + d] = accW[r];
    g_ceffp[t * 256 + d] = accC;
}

__global__ void pk3a(const float* __restrict__ b_fc2) {
    const int m = threadIdx.x;
    float s = b_fc2[m];
    #pragma unroll
    for (int t = 0; t < 12; t++) s += g_ceffp[t * 256 + m];
    g_ceff[m] = s;
}

__global__ void pk3b(const float* __restrict__ W_fc3, const float* __restrict__ b_fc3) {
    const int d = threadIdx.x;
    if (blockIdx.x < 48) {
        const int i = blockIdx.x;
        float a0 = 0.f, a1 = 0.f, a2 = 0.f, a3 = 0.f;
        #pragma unroll 4
        for (int m = 0; m < 256; m += 4) {
            a0 += g_Weff[i * 256 + m + 0] * W_fc3[(m + 0) * 256 + d];
            a1 += g_Weff[i * 256 + m + 1] * W_fc3[(m + 1) * 256 + d];
            a2 += g_Weff[i * 256 + m + 2] * W_fc3[(m + 2) * 256 + d];
            a3 += g_Weff[i * 256 + m + 3] * W_fc3[(m + 3) * 256 + d];
        }
        g_G[i * 256 + d] = (a0 + a1) + (a2 + a3);
    } else {
        float a0 = b_fc3[d], a1 = 0.f, a2 = 0.f, a3 = 0.f;
        #pragma unroll 4
        for (int m = 0; m < 256; m += 4) {
            a0 += g_ceff[m + 0] * W_fc3[(m + 0) * 256 + d];
            a1 += g_ceff[m + 1] * W_fc3[(m + 1) * 256 + d];
            a2 += g_ceff[m + 2] * W_fc3[(m + 2) * 256 + d];
            a3 += g_ceff[m + 3] * W_fc3[(m + 3) * 256 + d];
        }
        float acc = (a0 + a1) + (a2 + a3);
        #pragma unroll
        for (int n = 0; n < 11; n++) g_cb[n * 256 + d] = acc + W_fc3[(256 + n) * 256 + d];
    }
}

// split-transpose weights: out[n][k] (hi, lo) from W[k][n]
__global__ void wt_build2(const float* __restrict__ W, __nv_bfloat16* __restrict__ hi,
                          __nv_bfloat16* __restrict__ lo, int K, int N) {
    int idx = blockIdx.x * 256 + threadIdx.x;
    if (idx >= N * K) return;
    int n = idx / K, k = idx % K;
    float w = W[(size_t)k * N + n];
    __nv_bfloat16 h, l;
    split2(w, h, l);
    hi[idx] = h; lo[idx] = l;
}

// convert past_feature fp32 -> bf16 hi/lo
__global__ void cvt_past(const float* __restrict__ past) {
    size_t total = (size_t)BN_ROWS * 960 / 4;
    for (size_t i = (size_t)blockIdx.x * blockDim.x + threadIdx.x; i < total;
         i += (size_t)gridDim.x * blockDim.x) {
        float4 f = ((const float4*)past)[i];
        __nv_bfloat16 h0, h1, h2, h3, l0, l1, l2, l3;
        split2(f.x, h0, l0); split2(f.y, h1, l1);
        split2(f.z, h2, l2); split2(f.w, h3, l3);
        ((__nv_bfloat162*)g_past_hi)[2 * i]     = __nv_bfloat162(h0, h1);
        ((__nv_bfloat162*)g_past_hi)[2 * i + 1] = __nv_bfloat162(h2, h3);
        ((__nv_bfloat162*)g_past_lo)[2 * i]     = __nv_bfloat162(l0, l1);
        ((__nv_bfloat162*)g_past_lo)[2 * i + 1] = __nv_bfloat162(l2, l3);
    }
}

// ---------------- per-scene kernel (writes bf16 hi/lo) ----------------
__global__ void __launch_bounds__(256)
scene_kernel(const float* __restrict__ inputs) {
    __shared__ float in_s[11 * 48];
    __shared__ float ft[11 * 256];
    __shared__ float dot_s[121];
    __shared__ float corr_s[121];
    __shared__ float attn_s[121];
    __shared__ float arow_s[121];
    __shared__ float nrm[11];
    __shared__ float thr_s;

    const int b = blockIdx.x, tid = threadIdx.x;
    const float* ip = inputs + (size_t)b * 11 * 48;
    for (int i = tid; i < 528; i += 256) in_s[i] = ip[i];
    __syncthreads();

    float acc[11];
    #pragma unroll
    for (int n = 0; n < 11; n++) acc[n] = g_cb[n * 256 + tid];
    for (int k = 0; k < 48; k++) {
        float g = g_G[k * 256 + tid];
        #pragma unroll
        for (int n = 0; n < 11; n++) acc[n] += in_s[n * 48 + k] * g;
    }
    const size_t rowbase = (size_t)b * 11;
    #pragma unroll
    for (int n = 0; n < 11; n++) {
        ft[n * 256 + tid] = acc[n];
        __nv_bfloat16 h, l;
        split2(acc[n], h, l);
        size_t base = (rowbase + n) * 512 + tid;
        g_msg_hi[base] = h; g_msg_lo[base] = l;
        g_hpi_hi[base] = h; g_hpi_lo[base] = l;
    }
    __syncthreads();

    const int warp = tid >> 5, lane = tid & 31;
    for (int p = warp; p < 121; p += 8) {
        int n = p / 11, m = p % 11;
        if (m < n) continue;
        float s = 0.f;
        #pragma unroll
        for (int i = 0; i < 8; i++)
            s += ft[n * 256 + lane + 32 * i] * ft[m * 256 + lane + 32 * i];
        #pragma unroll
        for (int o = 16; o > 0; o >>= 1) s += __shfl_down_sync(0xffffffffu, s, o);
        if (lane == 0) { dot_s[n * 11 + m] = s; dot_s[m * 11 + n] = s; }
    }
    __syncthreads();
    if (tid < 11) nrm[tid] = sqrtf(dot_s[tid * 11 + tid]);
    __syncthreads();
    if (tid < 121) {
        int n = tid / 11, m = tid % 11;
        corr_s[tid] = dot_s[tid] / (nrm[n] * nrm[m]);
    }
    __syncthreads();
    if (tid == 0) {
        float a = corr_s[0];
        for (int i = 1; i < 121; i++) a = fminf(a, corr_s[i]);
        float thr;
        if (a < 0.4f)                  thr = 0.4f;
        else if (a > 0.4f && a < 0.6f) thr = a + 0.1f;
        else                           thr = a + 0.03f;
        thr_s = thr;
    }
    __syncthreads();
    if (tid < 11) {
        const int n = tid;
        const float thr = thr_s;
        float rs = 0.f;
        #pragma unroll
        for (int m = 0; m < 11; m++) rs += (corr_s[n * 11 + m] >= thr) ? 1.0f : 0.0f;
        const float inv = 1.0f / fmaxf(rs, 1.0f);
        #pragma unroll
        for (int m = 0; m < 11; m++)
            arow_s[n * 11 + m] = (corr_s[n * 11 + m] >= thr) ? inv : 0.0f;
        const float sc = 0.0625f;
        float mx = -1e30f;
        #pragma unroll
        for (int m = 0; m < 11; m++) mx = fmaxf(mx, dot_s[n * 11 + m] * sc);
        float e[11], se = 0.f;
        #pragma unroll
        for (int m = 0; m < 11; m++) { e[m] = expf(dot_s[n * 11 + m] * sc - mx); se += e[m]; }
        const float is = 1.0f / se;
        #pragma unroll
        for (int m = 0; m < 11; m++) attn_s[n * 11 + m] = e[m] * is;
    }
    __syncthreads();
    #pragma unroll
    for (int n = 0; n < 11; n++) {
        float a = 0.f, hh = 0.f;
        #pragma unroll
        for (int m = 0; m < 11; m++) {
            float f = ft[m * 256 + tid];
            a  += attn_s[n * 11 + m] * f;
            hh += arow_s[n * 11 + m] * f;
        }
        size_t base = (rowbase + n) * 512 + 256 + tid;
        __nv_bfloat16 h, l;
        split2(a, h, l);  g_msg_hi[base] = h; g_msg_lo[base] = l;
        split2(hh, h, l); g_hpi_hi[base] = h; g_hpi_lo[base] = l;
    }
}

// ---------------- generic tensor-core GEMM (single K pass, 3-term split) ----------------
// out = act(A @ W + bias); A given as bf16 hi/lo [rows][K]; W as Bt hi/lo [N][K].
template<int NTILE>
__global__ void __launch_bounds__(256)
k_mma(const __nv_bfloat16* __restrict__ Ahi, const __nv_bfloat16* __restrict__ Alo,
      const __nv_bfloat16* __restrict__ Bhi, const __nv_bfloat16* __restrict__ Blo,
      const float* __restrict__ bias,
      __nv_bfloat16* __restrict__ outHi, __nv_bfloat16* __restrict__ outLo,
      int K, int N, int relu) {
    constexpr int NF = NTILE / 16;
    constexpr int STAGE = 32768 + NTILE * 256;
    extern __shared__ char smx[];
    const uint32_t sb = smem_u32(smx);
    const int tid = threadIdx.x, lane = tid & 31, wid = tid >> 5;
    const int wm = wid >> 1, wn = wid & 1;
    const int m0 = blockIdx.y * 128, n0 = blockIdx.x * NTILE;
    const int NIT = K / 64;
    const int t4 = lane >> 3;
    const int aRow = (lane & 7) + (t4 & 1) * 8;
    const int aK8  = (t4 >> 1) * 8;
    const int bNl  = (t4 >> 1) * 8 + (lane & 7);
    const int bK8  = (t4 & 1) * 8;

    auto issue = [&](int it) {
        const int kk = it * 64, buf = it & 1;
        const uint32_t sA = sb + buf * STAGE;
        #pragma unroll
        for (int v = 0; v < 8; v++) {
            int idx = tid + v * 256;
            int tile = idx >> 10;
            int rr = (idx >> 3) & 127;
            int g = idx & 7;
            const __nv_bfloat16* s = (tile ? Alo : Ahi) + (size_t)(m0 + rr) * K + kk + g * 8;
            cp16(sA + tile * 16384 + SWZ((uint32_t)(rr * 128 + g * 16)), s);
        }
        #pragma unroll
        for (int v = 0; v < NTILE / 16; v++) {
            int idx = tid + v * 256;
            int tile = (idx >= NTILE * 8);
            int ii = tile ? idx - NTILE * 8 : idx;
            int rr = ii >> 3, g = ii & 7;
            const __nv_bfloat16* s = (tile ? Blo : Bhi) + (size_t)(n0 + rr) * K + kk + g * 8;
            cp16(sA + 32768 + tile * (NTILE * 128) + SWZ((uint32_t)(rr * 128 + g * 16)), s);
        }
        CP_COMMIT();
    };

    float c[2][NF][4];
    #pragma unroll
    for (int mi = 0; mi < 2; mi++)
        #pragma unroll
        for (int f = 0; f < NF; f++)
            #pragma unroll
            for (int q = 0; q < 4; q++) c[mi][f][q] = 0.f;

    issue(0);
    for (int it = 0; it < NIT; it++) {
        if (it + 1 < NIT) { issue(it + 1); CP_WAIT(1); } else { CP_WAIT(0); }
        __syncthreads();
        const uint32_t sA = sb + (it & 1) * STAGE;
        const uint32_t sBh = sA + 32768, sBl = sBh + NTILE * 128;
        #pragma unroll
        for (int k16 = 0; k16 < 4; k16++) {
            uint32_t ah[2][4], al[2][4], bh[NF][2], bl[NF][2];
            #pragma unroll
            for (int mi = 0; mi < 2; mi++) {
                uint32_t off = (uint32_t)((wm * 32 + mi * 16 + aRow) * 128 + k16 * 32 + aK8 * 2);
                ldm_x4(ah[mi], sA + SWZ(off));
                ldm_x4(al[mi], sA + 16384 + SWZ(off));
            }
            #pragma unroll
            for (int fp = 0; fp < NF / 2; fp++) {
                uint32_t off = (uint32_t)((wn * (NTILE / 2) + fp * 16 + bNl) * 128 + k16 * 32 + bK8 * 2);
                uint32_t r4[4];
                ldm_x4(r4, sBh + SWZ(off));
                bh[2 * fp][0] = r4[0]; bh[2 * fp][1] = r4[1];
                bh[2 * fp + 1][0] = r4[2]; bh[2 * fp + 1][1] = r4[3];
                ldm_x4(r4, sBl + SWZ(off));
                bl[2 * fp][0] = r4[0]; bl[2 * fp][1] = r4[1];
                bl[2 * fp + 1][0] = r4[2]; bl[2 * fp + 1][1] = r4[3];
            }
            #pragma unroll
            for (int mi = 0; mi < 2; mi++)
                #pragma unroll
                for (int f = 0; f < NF; f++) mma16816(c[mi][f], ah[mi], bh[f]);
            #pragma unroll
            for (int mi = 0; mi < 2; mi++)
                #pragma unroll
                for (int f = 0; f < NF; f++) mma16816(c[mi][f], ah[mi], bl[f]);
            #pragma unroll
            for (int mi = 0; mi < 2; mi++)
                #pragma unroll
                for (int f = 0; f < NF; f++) mma16816(c[mi][f], al[mi], bh[f]);
        }
        __syncthreads();
    }

    // epilogue: bias (+relu) -> split hi/lo bf16 -> global
    const int gID = lane >> 2, tig = lane & 3;
    #pragma unroll
    for (int mi = 0; mi < 2; mi++) {
        const int r0 = m0 + wm * 32 + mi * 16 + gID;
        #pragma unroll
        for (int f = 0; f < NF; f++) {
            const int col = n0 + wn * (NTILE / 2) + f * 8 + tig * 2;
            const float b0 = bias[col], b1 = bias[col + 1];
            float v00 = c[mi][f][0] + b0, v01 = c[mi][f][1] + b1;
            float v10 = c[mi][f][2] + b0, v11 = c[mi][f][3] + b1;
            if (relu) {
                v00 = fmaxf(v00, 0.f); v01 = fmaxf(v01, 0.f);
                v10 = fmaxf(v10, 0.f); v11 = fmaxf(v11, 0.f);
            }
            __nv_bfloat16 h0, h1, l0, l1;
            split2(v00, h0, l0); split2(v01, h1, l1);
            *(__nv_bfloat162*)(outHi + (size_t)r0 * N + col) = __nv_bfloat162(h0, h1);
            *(__nv_bfloat162*)(outLo + (size_t)r0 * N + col) = __nv_bfloat162(l0, l1);
            split2(v10, h0, l0); split2(v11, h1, l1);
            *(__nv_bfloat162*)(outHi + (size_t)(r0 + 8) * N + col) = __nv_bfloat162(h0, h1);
            *(__nv_bfloat162*)(outLo + (size_t)(r0 + 8) * N + col) = __nv_bfloat162(l0, l1);
        }
    }
}

// ---------------- final GEMM: gathered A, fused qz epilogue ----------------
// h = relu([past|ftraj|inter|feat] @ W_out + b_out); out = h @ W_qz + b_qz
#define FSTAGE 65536   // 32K A (hi+lo) + 32K B (hi+lo), NTILE=128
__global__ void __launch_bounds__(256)
k_final(const float* __restrict__ b_out, const float* __restrict__ b_qz,
        float* __restrict__ out) {
    constexpr int NF = 8;
    extern __shared__ char smx[];
    const uint32_t sb = smem_u32(smx);
    const int tid = threadIdx.x, lane = tid & 31, wid = tid >> 5;
    const int wm = wid >> 1, wn = wid & 1;
    const int m0 = blockIdx.x * 128;
    const int NIT = 24;  // K = 1536
    const int t4 = lane >> 3;
    const int aRow = (lane & 7) + (t4 & 1) * 8;
    const int aK8  = (t4 >> 1) * 8;
    const int bNl  = (t4 >> 1) * 8 + (lane & 7);
    const int bK8  = (t4 & 1) * 8;

    auto issue = [&](int it) {
        const int kk = it * 64, buf = it & 1;
        const uint32_t sA = sb + buf * FSTAGE;
        const __nv_bfloat16 *shi, *slo;
        int stride, off;
        if (kk < 960)       { shi = g_past_hi; slo = g_past_lo; stride = 960; off = kk; }
        else if (kk < 1216) { shi = g_msg_hi;  slo = g_msg_lo;  stride = 512; off = kk - 960; }
        else if (kk < 1472) { shi = g_int_hi;  slo = g_int_lo;  stride = 256; off = kk - 1216; }
        else                { shi = g_fea_hi;  slo = g_fea_lo;  stride = 64;  off = kk - 1472; }
        #pragma unroll
        for (int v = 0; v < 8; v++) {
            int idx = tid + v * 256;
            int tile = idx >> 10;
            int rr = (idx >> 3) & 127;
            int g = idx & 7;
            const __nv_bfloat16* s = (tile ? slo : shi) + (size_t)(m0 + rr) * stride + off + g * 8;
            cp16(sA + tile * 16384 + SWZ((uint32_t)(rr * 128 + g * 16)), s);
        }
        #pragma unroll
        for (int v = 0; v < 8; v++) {
            int idx = tid + v * 256;
            int tile = idx >> 10;
            int rr = (idx >> 3) & 127;
            int g = idx & 7;
            const __nv_bfloat16* s = (tile ? g_Wout_lo : g_Wout_hi) + (size_t)rr * 1536 + kk + g * 8;
            cp16(sA + 32768 + tile * 16384 + SWZ((uint32_t)(rr * 128 + g * 16)), s);
        }
        CP_COMMIT();
    };

    // stage W_qz tiles once (region at 2*FSTAGE): hi[ch0,ch1] then lo[ch0,ch1]
    #pragma unroll
    for (int v = 0; v < 8; v++) {
        int idx = tid + v * 256;          // 0..2047
        int half = idx >> 10, rem = idx & 1023, ch = rem >> 9, ii = rem & 511;
        int rr = ii >> 3, g = ii & 7;
        const __nv_bfloat16* s = (half ? g_Wqz_lo : g_Wqz_hi) + rr * 128 + ch * 64 + g * 8;
        cp16(sb + 2 * FSTAGE + half * 16384 + ch * 8192 + SWZ((uint32_t)(rr * 128 + g * 16)), s);
    }

    float c[2][NF][4];
    #pragma unroll
    for (int mi = 0; mi < 2; mi++)
        #pragma unroll
        for (int f = 0; f < NF; f++)
            #pragma unroll
            for (int q = 0; q < 4; q++) c[mi][f][q] = 0.f;

    issue(0);
    for (int it = 0; it < NIT; it++) {
        if (it + 1 < NIT) { issue(it + 1); CP_WAIT(1); } else { CP_WAIT(0); }
        __syncthreads();
        const uint32_t sA = sb + (it & 1) * FSTAGE;
        const uint32_t sBh = sA + 32768, sBl = sA + 49152;
        #pragma unroll
        for (int k16 = 0; k16 < 4; k16++) {
            uint32_t ah[2][4], al[2][4], bh[NF][2], bl[NF][2];
            #pragma unroll
            for (int mi = 0; mi < 2; mi++) {
                uint32_t off = (uint32_t)((wm * 32 + mi * 16 + aRow) * 128 + k16 * 32 + aK8 * 2);
                ldm_x4(ah[mi], sA + SWZ(off));
                ldm_x4(al[mi], sA + 16384 + SWZ(off));
            }
            #pragma unroll
            for (int fp = 0; fp < NF / 2; fp++) {
                uint32_t off = (uint32_t)((wn * 64 + fp * 16 + bNl) * 128 + k16 * 32 + bK8 * 2);
                uint32_t r4[4];
                ldm_x4(r4, sBh + SWZ(off));
                bh[2 * fp][0] = r4[0]; bh[2 * fp][1] = r4[1];
                bh[2 * fp + 1][0] = r4[2]; bh[2 * fp + 1][1] = r4[3];
                ldm_x4(r4, sBl + SWZ(off));
                bl[2 * fp][0] = r4[0]; bl[2 * fp][1] = r4[1];
                bl[2 * fp + 1][0] = r4[2]; bl[2 * fp + 1][1] = r4[3];
            }
            #pragma unroll
            for (int mi = 0; mi < 2; mi++)
                #pragma unroll
                for (int f = 0; f < NF; f++) mma16816(c[mi][f], ah[mi], bh[f]);
            #pragma unroll
            for (int mi = 0; mi < 2; mi++)
                #pragma unroll
                for (int f = 0; f < NF; f++) mma16816(c[mi][f], ah[mi], bl[f]);
            #pragma unroll
            for (int mi = 0; mi < 2; mi++)
                #pragma unroll
                for (int f = 0; f < NF; f++) mma16816(c[mi][f], al[mi], bh[f]);
        }
        __syncthreads();
    }

    // epilogue 1: h = relu(c + b_out) -> split -> Hs tiles in smem
    // HsHi chunk ch at sb + ch*16384 ; HsLo chunk ch at sb + 32768 + ch*16384
    const int gID = lane >> 2, tig = lane & 3;
    __syncthreads();
    #pragma unroll
    for (int mi = 0; mi < 2; mi++) {
        const int r0 = wm * 32 + mi * 16 + gID;
        #pragma unroll
        for (int f = 0; f < NF; f++) {
            const int col = wn * 64 + f * 8 + tig * 2;
            const float b0 = b_out[col], b1 = b_out[col + 1];
            float v00 = fmaxf(c[mi][f][0] + b0, 0.f), v01 = fmaxf(c[mi][f][1] + b1, 0.f);
            float v10 = fmaxf(c[mi][f][2] + b0, 0.f), v11 = fmaxf(c[mi][f][3] + b1, 0.f);
            const int ch = col >> 6;
            const uint32_t in0 = SWZ((uint32_t)(r0 * 128 + (col & 63) * 2));
            const uint32_t in1 = SWZ((uint32_t)((r0 + 8) * 128 + (col & 63) * 2));
            __nv_bfloat16 h0, h1, l0, l1;
            split2(v00, h0, l0); split2(v01, h1, l1);
            *(__nv_bfloat162*)(smx + ch * 16384 + in0) = __nv_bfloat162(h0, h1);
            *(__nv_bfloat162*)(smx + 32768 + ch * 16384 + in0) = __nv_bfloat162(l0, l1);
            split2(v10, h0, l0); split2(v11, h1, l1);
            *(__nv_bfloat162*)(smx + ch * 16384 + in1) = __nv_bfloat162(h0, h1);
            *(__nv_bfloat162*)(smx + 32768 + ch * 16384 + in1) = __nv_bfloat162(l0, l1);
        }
    }
    __syncthreads();

    // epilogue 2: out = h @ W_qz + b_qz (via mma over smem tiles)
    float c2[2][4][4];
    #pragma unroll
    for (int mi = 0; mi < 2; mi++)
        #pragma unroll
        for (int f = 0; f < 4; f++)
            #pragma unroll
            for (int q = 0; q < 4; q++) c2[mi][f][q] = 0.f;
    #pragma unroll
    for (int ch = 0; ch < 2; ch++) {
        const uint32_t sAh = sb + ch * 16384, sAl = sb + 32768 + ch * 16384;
        const uint32_t sBh = sb + 2 * FSTAGE + ch * 8192;
        const uint32_t sBl = sb + 2 * FSTAGE + 16384 + ch * 8192;
        #pragma unroll
        for (int k16 = 0; k16 < 4; k16++) {
            uint32_t ah[2][4], al[2][4], bh[4][2], bl[4][2];
            #pragma unroll
            for (int mi = 0; mi < 2; mi++) {
                uint32_t off = (uint32_t)((wm * 32 + mi * 16 + aRow) * 128 + k16 * 32 + aK8 * 2);
                ldm_x4(ah[mi], sAh + SWZ(off));
                ldm_x4(al[mi], sAl + SWZ(off));
            }
            #pragma unroll
            for (int fp = 0; fp < 2; fp++) {
                uint32_t off = (uint32_t)((wn * 32 + fp * 16 + bNl) * 128 + k16 * 32 + bK8 * 2);
                uint32_t r4[4];
                ldm_x4(r4, sBh + SWZ(off));
                bh[2 * fp][0] = r4[0]; bh[2 * fp][1] = r4[1];
                bh[2 * fp + 1][0] = r4[2]; bh[2 * fp + 1][1] = r4[3];
                ldm_x4(r4, sBl + SWZ(off));
                bl[2 * fp][0] = r4[0]; bl[2 * fp][1] = r4[1];
                bl[2 * fp + 1][0] = r4[2]; bl[2 * fp + 1][1] = r4[3];
            }
            #pragma unroll
            for (int mi = 0; mi < 2; mi++)
                #pragma unroll
                for (int f = 0; f < 4; f++) mma16816(c2[mi][f], ah[mi], bh[f]);
            #pragma unroll
            for (int mi = 0; mi < 2; mi++)
                #pragma unroll
                for (int f = 0; f < 4; f++) mma16816(c2[mi][f], ah[mi], bl[f]);
            #pragma unroll
            for (int mi = 0; mi < 2; mi++)
                #pragma unroll
                for (int f = 0; f < 4; f++) mma16816(c2[mi][f], al[mi], bh[f]);
        }
    }
    #pragma unroll
    for (int mi = 0; mi < 2; mi++) {
        const int r0 = m0 + wm * 32 + mi * 16 + gID;
        #pragma unroll
        for (int f = 0; f < 4; f++) {
            const int col = wn * 32 + f * 8 + tig * 2;
            const float b0 = b_qz[col], b1 = b_qz[col + 1];
            *(float2*)(out + (size_t)r0 * 64 + col) =
                make_float2(c2[mi][f][0] + b0, c2[mi][f][1] + b1);
            *(float2*)(out + (size_t)(r0 + 8) * 64 + col) =
                make_float2(c2[mi][f][2] + b0, c2[mi][f][3] + b1);
        }
    }
}

// ---------------- launch ----------------
extern "C" void kernel_launch(void* const* d_in, const int* in_sizes, int n_in,
                              void* d_out, int out_size) {
    const float* inputs = (const float*)d_in[0];
    const float* past   = (const float*)d_in[1];
    const float* W_in   = (const float*)d_in[2];
    const float* b_in   = (const float*)d_in[3];
    const float* W_pos  = (const float*)d_in[4];
    const float* b_pos  = (const float*)d_in[5];
    const float* W_fc2  = (const float*)d_in[6];
    const float* b_fc2  = (const float*)d_in[7];
    const float* W_fc3  = (const float*)d_in[8];
    const float* b_fc3  = (const float*)d_in[9];
    const float* W_msg  = (const float*)d_in[10];
    const float* b_msg  = (const float*)d_in[11];
    const float* W_hyp  = (const float*)d_in[12];
    const float* b_hyp  = (const float*)d_in[13];
    const float* W_line = (const float*)d_in[14];
    const float* W_out  = (const float*)d_in[15];
    const float* b_out  = (const float*)d_in[16];
    const float* W_qz   = (const float*)d_in[17];
    const float* b_qz   = (const float*)d_in[18];
    float* out = (float*)d_out;

    void *pMsgHi, *pMsgLo, *pHpiHi, *pHpiLo, *pIntHi, *pIntLo;
    void *pHypHi, *pHypLo, *pFeaHi, *pFeaLo, *pZero;
    void *pWmsgHi, *pWmsgLo, *pWhypHi, *pWhypLo, *pWoutHi, *pWoutLo;
    void *pWlinHi, *pWlinLo, *pWqzHi, *pWqzLo;
    cudaGetSymbolAddress(&pMsgHi, g_msg_hi);   cudaGetSymbolAddress(&pMsgLo, g_msg_lo);
    cudaGetSymbolAddress(&pHpiHi, g_hpi_hi);   cudaGetSymbolAddress(&pHpiLo, g_hpi_lo);
    cudaGetSymbolAddress(&pIntHi, g_int_hi);   cudaGetSymbolAddress(&pIntLo, g_int_lo);
    cudaGetSymbolAddress(&pHypHi, g_hyp_hi);   cudaGetSymbolAddress(&pHypLo, g_hyp_lo);
    cudaGetSymbolAddress(&pFeaHi, g_fea_hi);   cudaGetSymbolAddress(&pFeaLo, g_fea_lo);
    cudaGetSymbolAddress(&pZero, g_zero64);
    cudaGetSymbolAddress(&pWmsgHi, g_Wmsg_hi); cudaGetSymbolAddress(&pWmsgLo, g_Wmsg_lo);
    cudaGetSymbolAddress(&pWhypHi, g_Whyp_hi); cudaGetSymbolAddress(&pWhypLo, g_Whyp_lo);
    cudaGetSymbolAddress(&pWoutHi, g_Wout_hi); cudaGetSymbolAddress(&pWoutLo, g_Wout_lo);
    cudaGetSymbolAddress(&pWlinHi, g_Wlin_hi); cudaGetSymbolAddress(&pWlinLo, g_Wlin_lo);
    cudaGetSymbolAddress(&pWqzHi, g_Wqz_hi);   cudaGetSymbolAddress(&pWqzLo, g_Wqz_lo);

    cudaFuncSetAttribute(k_mma<128>, cudaFuncAttributeMaxDynamicSharedMemorySize, 131072);
    cudaFuncSetAttribute(k_mma<64>,  cudaFuncAttributeMaxDynamicSharedMemorySize, 98304);
    cudaFuncSetAttribute(k_final,    cudaFuncAttributeMaxDynamicSharedMemorySize, 163840);

    pk1<<<1, 256>>>(W_in, b_in, W_pos, b_pos);
    pk2<<<12, 256>>>(W_fc2);
    pk3a<<<1, 256>>>(b_fc2);
    pk3b<<<49, 256>>>(W_fc3, b_fc3);
    wt_build2<<<(256 * 512 + 255) / 256, 256>>>(W_msg, (__nv_bfloat16*)pWmsgHi,
                                                (__nv_bfloat16*)pWmsgLo, 512, 256);
    wt_build2<<<(256 * 512 + 255) / 256, 256>>>(W_hyp, (__nv_bfloat16*)pWhypHi,
                                                (__nv_bfloat16*)pWhypLo, 512, 256);
    wt_build2<<<(128 * 1536 + 255) / 256, 256>>>(W_out, (__nv_bfloat16*)pWoutHi,
                                                 (__nv_bfloat16*)pWoutLo, 1536, 128);
    wt_build2<<<(64 * 256 + 255) / 256, 256>>>(W_line, (__nv_bfloat16*)pWlinHi,
                                               (__nv_bfloat16*)pWlinLo, 256, 64);
    wt_build2<<<(64 * 128 + 255) / 256, 256>>>(W_qz, (__nv_bfloat16*)pWqzHi,
                                               (__nv_bfloat16*)pWqzLo, 128, 64);
    cvt_past<<<2048, 256>>>(past);
    scene_kernel<<<B_SZ, 256>>>(inputs);

    // inter = relu(msgin @ W_msg + b_msg)
    k_mma<128><<<dim3(2, MTILES), 256, 131072>>>(
        (const __nv_bfloat16*)pMsgHi, (const __nv_bfloat16*)pMsgLo,
        (const __nv_bfloat16*)pWmsgHi, (const __nv_bfloat16*)pWmsgLo, b_msg,
        (__nv_bfloat16*)pIntHi, (__nv_bfloat16*)pIntLo, 512, 256, 1);
    // hyp = relu(hypin @ W_hyp + b_hyp)
    k_mma<128><<<dim3(2, MTILES), 256, 131072>>>(
        (const __nv_bfloat16*)pHpiHi, (const __nv_bfloat16*)pHpiLo,
        (const __nv_bfloat16*)pWhypHi, (const __nv_bfloat16*)pWhypLo, b_hyp,
        (__nv_bfloat16*)pHypHi, (__nv_bfloat16*)pHypLo, 512, 256, 1);
    // feat = hyp @ W_line
    k_mma<64><<<dim3(1, MTILES), 256, 98304>>>(
        (const __nv_bfloat16*)pHypHi, (const __nv_bfloat16*)pHypLo,
        (const __nv_bfloat16*)pWlinHi, (const __nv_bfloat16*)pWlinLo, (const float*)pZero,
        (__nv_bfloat16*)pFeaHi, (__nv_bfloat16*)pFeaLo, 256, 64, 0);
    // h = relu(gather @ W_out + b_out); out = h @ W_qz + b_qz
    k_final<<<MTILES, 256, 163840>>>(b_out, b_qz, out);
}

// round 6
// speedup vs baseline: 3.3821x; 1.7624x over previous
#include <cuda_runtime.h>
#include <cuda_fp16.h>
#include <math.h>
#include <stdint.h>

// Problem constants
#define B_SZ   4096
#define N_AG   11
#define BN_ROWS (B_SZ * N_AG)      // 45056
#define MTILES  (BN_ROWS / 128)    // 352

// ---------------- device scratch ----------------
__device__ float g_Weff[48 * 256];
__device__ float g_ceffp[12 * 256];
__device__ float g_G[48 * 256];
__device__ float g_cb[11 * 256];
__device__ float g_zero64[64];     // zero bias (never written)

// fp16 activations
__device__ __half g_past_h[(size_t)BN_ROWS * 960];
__device__ __half g_ft [(size_t)BN_ROWS * 256];
__device__ __half g_agg[(size_t)BN_ROWS * 256];
__device__ __half g_hag[(size_t)BN_ROWS * 256];
__device__ __half g_int[(size_t)BN_ROWS * 256];
__device__ __half g_hyp[(size_t)BN_ROWS * 256];
__device__ __half g_fea[(size_t)BN_ROWS * 64];
// fp16 transposed weights [n][K]
__device__ __half g_Wmsg_t[256 * 512];
__device__ __half g_Whyp_t[256 * 512];
__device__ __half g_Wout_t[128 * 1536];
__device__ __half g_Wlin_t[64 * 256];
__device__ __half g_Wqz_t [64 * 128];

// ---------------- helpers ----------------
#define SWZ(o) ((o) ^ (((o) >> 3) & 0x70))
__device__ __forceinline__ uint32_t smem_u32(const void* p) {
    uint32_t a;
    asm("{ .reg .u64 t; cvta.to.shared.u64 t, %1; cvt.u32.u64 %0, t; }" : "=r"(a) : "l"(p));
    return a;
}
__device__ __forceinline__ void ldm_x4(uint32_t* r, uint32_t addr) {
    asm volatile("ldmatrix.sync.aligned.m8n8.x4.shared.b16 {%0,%1,%2,%3}, [%4];"
                 : "=r"(r[0]), "=r"(r[1]), "=r"(r[2]), "=r"(r[3]) : "r"(addr));
}
__device__ __forceinline__ void mma_f16(float* c, const uint32_t* a, const uint32_t* b) {
    asm("mma.sync.aligned.m16n8k16.row.col.f32.f16.f16.f32 "
        "{%0,%1,%2,%3},{%4,%5,%6,%7},{%8,%9},{%0,%1,%2,%3};"
        : "+f"(c[0]), "+f"(c[1]), "+f"(c[2]), "+f"(c[3])
        : "r"(a[0]), "r"(a[1]), "r"(a[2]), "r"(a[3]), "r"(b[0]), "r"(b[1]));
}
__device__ __forceinline__ void cp16(uint32_t dst, const void* src) {
    asm volatile("cp.async.cg.shared.global [%0], [%1], 16;"
                 :: "r"(dst), "l"(__cvta_generic_to_global(src)) : "memory");
}
#define CP_COMMIT() asm volatile("cp.async.commit_group;" ::: "memory")
#define CP_WAIT(n)  asm volatile("cp.async.wait_group %0;" :: "n"(n) : "memory")

// ---------------- pk12: folded front-end (pk1 + pk2 merged; 12 blocks) ----------------
__global__ void __launch_bounds__(256)
pk12(const float* __restrict__ W_in, const float* __restrict__ b_in,
     const float* __restrict__ W_pos, const float* __restrict__ b_pos,
     const float* __restrict__ W_fc2) {
    __shared__ float pe[256];
    __shared__ float sM4[4 * 256];
    __shared__ float sbt[256];
    const int t = blockIdx.x, d = threadIdx.x;
    {
        int k = d, i2 = k & ~1;
        float div = expf(-logf(10000.0f) * (float)i2 / 256.0f);
        float arg = (float)t * div;
        pe[k] = (k & 1) ? cosf(arg) : sinf(arg);
    }
    __syncthreads();
    float m[4] = {0.f, 0.f, 0.f, 0.f};
    float bb = 0.f;
    for (int k = 0; k < 256; k++) {
        float w = W_pos[k * 256 + d];
        #pragma unroll
        for (int r = 0; r < 4; r++) m[r] += W_in[r * 256 + k] * w;
        bb += b_in[k] * w;
    }
    float acc = bb + b_pos[d];
    for (int k = 0; k < 256; k++)
        acc += pe[k] * W_pos[(256 + k) * 256 + d];
    #pragma unroll
    for (int r = 0; r < 4; r++) sM4[r * 256 + d] = m[r];
    sbt[d] = acc;
    __syncthreads();
    float accW[4] = {0.f, 0.f, 0.f, 0.f};
    float accC = 0.f;
    #pragma unroll 4
    for (int mm = 0; mm < 256; mm++) {
        float w = W_fc2[(size_t)((t << 8) + mm) * 256 + d];
        #pragma unroll
        for (int r = 0; r < 4; r++) accW[r] += sM4[r * 256 + mm] * w;
        accC += sbt[mm] * w;
    }
    #pragma unroll
    for (int r = 0; r < 4; r++) g_Weff[(t * 4 + r) * 256 + d] = accW[r];
    g_ceffp[t * 256 + d] = accC;
}

// ---------------- pk3: fold fc3 (49 blocks; block 48 computes ceff inline) ----------------
__global__ void __launch_bounds__(256)
pk3(const float* __restrict__ W_fc3, const float* __restrict__ b_fc3,
    const float* __restrict__ b_fc2) {
    const int d = threadIdx.x;
    if (blockIdx.x < 48) {
        const int i = blockIdx.x;
        float a0 = 0.f, a1 = 0.f, a2 = 0.f, a3 = 0.f;
        #pragma unroll 4
        for (int m = 0; m < 256; m += 4) {
            a0 += g_Weff[i * 256 + m + 0] * W_fc3[(m + 0) * 256 + d];
            a1 += g_Weff[i * 256 + m + 1] * W_fc3[(m + 1) * 256 + d];
            a2 += g_Weff[i * 256 + m + 2] * W_fc3[(m + 2) * 256 + d];
            a3 += g_Weff[i * 256 + m + 3] * W_fc3[(m + 3) * 256 + d];
        }
        g_G[i * 256 + d] = (a0 + a1) + (a2 + a3);
    } else {
        __shared__ float ce[256];
        float s = b_fc2[d];
        #pragma unroll
        for (int t = 0; t < 12; t++) s += g_ceffp[t * 256 + d];
        ce[d] = s;
        __syncthreads();
        float a0 = b_fc3[d], a1 = 0.f, a2 = 0.f, a3 = 0.f;
        #pragma unroll 4
        for (int m = 0; m < 256; m += 4) {
            a0 += ce[m + 0] * W_fc3[(m + 0) * 256 + d];
            a1 += ce[m + 1] * W_fc3[(m + 1) * 256 + d];
            a2 += ce[m + 2] * W_fc3[(m + 2) * 256 + d];
            a3 += ce[m + 3] * W_fc3[(m + 3) * 256 + d];
        }
        float acc = (a0 + a1) + (a2 + a3);
        #pragma unroll
        for (int n = 0; n < 11; n++) g_cb[n * 256 + d] = acc + W_fc3[(256 + n) * 256 + d];
    }
}

// ---------------- prep: weight transposes (fp16) + past conversion ----------------
#define NB_W 512
#define NB_ALL 4096
__global__ void __launch_bounds__(256)
prep(const float* __restrict__ W_msg, const float* __restrict__ W_hyp,
     const float* __restrict__ W_out, const float* __restrict__ W_line,
     const float* __restrict__ W_qz,  const float* __restrict__ past) {
    if (blockIdx.x < NB_W) {
        const int stride = NB_W * 256;
        for (int idx = blockIdx.x * 256 + threadIdx.x; idx < 483328; idx += stride) {
            if (idx < 131072) {
                int n = idx >> 9, k = idx & 511;
                g_Wmsg_t[idx] = __float2half(W_msg[(size_t)k * 256 + n]);
            } else if (idx < 262144) {
                int i = idx - 131072;
                int n = i >> 9, k = i & 511;
                g_Whyp_t[i] = __float2half(W_hyp[(size_t)k * 256 + n]);
            } else if (idx < 458752) {
                int i = idx - 262144;
                int n = i / 1536, k = i % 1536;
                g_Wout_t[i] = __float2half(W_out[(size_t)k * 128 + n]);
            } else if (idx < 475136) {
                int i = idx - 458752;
                int n = i >> 8, k = i & 255;
                g_Wlin_t[i] = __float2half(W_line[(size_t)k * 64 + n]);
            } else {
                int i = idx - 475136;
                int n = i >> 7, k = i & 127;
                g_Wqz_t[i] = __float2half(W_qz[(size_t)k * 64 + n]);
            }
        }
    } else {
        const size_t total = (size_t)BN_ROWS * 960 / 4;
        const size_t stride = (size_t)(NB_ALL - NB_W) * 256;
        for (size_t i = (size_t)(blockIdx.x - NB_W) * 256 + threadIdx.x; i < total; i += stride) {
            float4 f = ((const float4*)past)[i];
            __half2 h0 = __float22half2_rn(make_float2(f.x, f.y));
            __half2 h1 = __float22half2_rn(make_float2(f.z, f.w));
            ((__half2*)g_past_h)[2 * i]     = h0;
            ((__half2*)g_past_h)[2 * i + 1] = h1;
        }
    }
}

// ---------------- per-scene kernel ----------------
__global__ void __launch_bounds__(256)
scene_kernel(const float* __restrict__ inputs) {
    __shared__ float in_s[11 * 48];
    __shared__ float ft[11 * 256];
    __shared__ float dot_s[121];
    __shared__ float corr_s[121];
    __shared__ float attn_s[121];
    __shared__ float arow_s[121];
    __shared__ float nrm[11];
    __shared__ float thr_s;

    const int b = blockIdx.x, tid = threadIdx.x;
    const float* ip = inputs + (size_t)b * 11 * 48;
    for (int i = tid; i < 528; i += 256) in_s[i] = ip[i];
    __syncthreads();

    float acc[11];
    #pragma unroll
    for (int n = 0; n < 11; n++) acc[n] = g_cb[n * 256 + tid];
    for (int k = 0; k < 48; k++) {
        float g = g_G[k * 256 + tid];
        #pragma unroll
        for (int n = 0; n < 11; n++) acc[n] += in_s[n * 48 + k] * g;
    }
    const size_t rowbase = (size_t)b * 11;
    #pragma unroll
    for (int n = 0; n < 11; n++) {
        ft[n * 256 + tid] = acc[n];
        g_ft[(rowbase + n) * 256 + tid] = __float2half(acc[n]);
    }
    __syncthreads();

    const int warp = tid >> 5, lane = tid & 31;
    for (int p = warp; p < 121; p += 8) {
        int n = p / 11, m = p % 11;
        if (m < n) continue;
        float s = 0.f;
        #pragma unroll
        for (int i = 0; i < 8; i++)
            s += ft[n * 256 + lane + 32 * i] * ft[m * 256 + lane + 32 * i];
        #pragma unroll
        for (int o = 16; o > 0; o >>= 1) s += __shfl_down_sync(0xffffffffu, s, o);
        if (lane == 0) { dot_s[n * 11 + m] = s; dot_s[m * 11 + n] = s; }
    }
    __syncthreads();
    if (tid < 11) nrm[tid] = sqrtf(dot_s[tid * 11 + tid]);
    __syncthreads();
    if (tid < 121) {
        int n = tid / 11, m = tid % 11;
        corr_s[tid] = dot_s[tid] / (nrm[n] * nrm[m]);
    }
    __syncthreads();
    if (tid == 0) {
        float a = corr_s[0];
        for (int i = 1; i < 121; i++) a = fminf(a, corr_s[i]);
        float thr;
        if (a < 0.4f)                  thr = 0.4f;
        else if (a > 0.4f && a < 0.6f) thr = a + 0.1f;
        else                           thr = a + 0.03f;
        thr_s = thr;
    }
    __syncthreads();
    if (tid < 11) {
        const int n = tid;
        const float thr = thr_s;
        float rs = 0.f;
        #pragma unroll
        for (int m = 0; m < 11; m++) rs += (corr_s[n * 11 + m] >= thr) ? 1.0f : 0.0f;
        const float inv = 1.0f / fmaxf(rs, 1.0f);
        #pragma unroll
        for (int m = 0; m < 11; m++)
            arow_s[n * 11 + m] = (corr_s[n * 11 + m] >= thr) ? inv : 0.0f;
        const float sc = 0.0625f;
        float mx = -1e30f;
        #pragma unroll
        for (int m = 0; m < 11; m++) mx = fmaxf(mx, dot_s[n * 11 + m] * sc);
        float e[11], se = 0.f;
        #pragma unroll
        for (int m = 0; m < 11; m++) { e[m] = expf(dot_s[n * 11 + m] * sc - mx); se += e[m]; }
        const float is = 1.0f / se;
        #pragma unroll
        for (int m = 0; m < 11; m++) attn_s[n * 11 + m] = e[m] * is;
    }
    __syncthreads();
    #pragma unroll
    for (int n = 0; n < 11; n++) {
        float a = 0.f, hh = 0.f;
        #pragma unroll
        for (int m = 0; m < 11; m++) {
            float f = ft[m * 256 + tid];
            a  += attn_s[n * 11 + m] * f;
            hh += arow_s[n * 11 + m] * f;
        }
        g_agg[(rowbase + n) * 256 + tid] = __float2half(a);
        g_hag[(rowbase + n) * 256 + tid] = __float2half(hh);
    }
}

// ---------------- fp16 tensor-core GEMM, 1-term, 3-stage cp.async pipeline ----------------
// out = act(A @ W + bias); A = [A1 | A2] fp16 (boundary K1); Bt fp16 [N][K].
template<int NTILE>
__global__ void __launch_bounds__(256)
k_mma(const __half* __restrict__ A1, const __half* __restrict__ A2,
      const __half* __restrict__ Bt, const float* __restrict__ bias,
      __half* __restrict__ out, int K, int K1, int N, int relu) {
    constexpr int NF = NTILE / 16;
    constexpr int STAGE = 16384 + NTILE * 128;
    extern __shared__ char smx[];
    const uint32_t sb = smem_u32(smx);
    const int tid = threadIdx.x, lane = tid & 31, wid = tid >> 5;
    const int wm = wid >> 1, wn = wid & 1;
    const int m0 = blockIdx.y * 128, n0 = blockIdx.x * NTILE;
    const int NIT = K / 64;
    const int K2 = K - K1;
    const int t4 = lane >> 3;
    const int aRow = (lane & 7) + (t4 & 1) * 8;
    const int aK8  = (t4 >> 1) * 8;
    const int bNl  = (t4 >> 1) * 8 + (lane & 7);
    const int bK8  = (t4 & 1) * 8;

    auto issue = [&](int it) {
        const int kk = it * 64;
        const uint32_t sA = sb + (it % 3) * STAGE;
        #pragma unroll
        for (int v = 0; v < 4; v++) {
            int idx = tid + v * 256;
            int rr = idx >> 3, g = idx & 7;
            const __half* s = (kk < K1)
                ? A1 + (size_t)(m0 + rr) * K1 + kk + g * 8
                : A2 + (size_t)(m0 + rr) * K2 + (kk - K1) + g * 8;
            cp16(sA + SWZ((uint32_t)(rr * 128 + g * 16)), s);
        }
        #pragma unroll
        for (int v = 0; v < NTILE / 32; v++) {
            int idx = tid + v * 256;
            int rr = idx >> 3, g = idx & 7;
            cp16(sA + 16384 + SWZ((uint32_t)(rr * 128 + g * 16)),
                 Bt + (size_t)(n0 + rr) * K + kk + g * 8);
        }
        CP_COMMIT();
    };

    float c[2][NF][4];
    #pragma unroll
    for (int mi = 0; mi < 2; mi++)
        #pragma unroll
        for (int f = 0; f < NF; f++)
            #pragma unroll
            for (int q = 0; q < 4; q++) c[mi][f][q] = 0.f;

    issue(0);
    if (NIT > 1) issue(1);
    for (int it = 0; it < NIT; it++) {
        if (it + 2 < NIT)      { issue(it + 2); CP_WAIT(2); }
        else if (it + 1 < NIT) { CP_WAIT(1); }
        else                   { CP_WAIT(0); }
        __syncthreads();
        const uint32_t sA = sb + (it % 3) * STAGE;
        const uint32_t sB = sA + 16384;
        #pragma unroll
        for (int k16 = 0; k16 < 4; k16++) {
            uint32_t a[2][4], bf[NF][2];
            #pragma unroll
            for (int mi = 0; mi < 2; mi++) {
                uint32_t off = (uint32_t)((wm * 32 + mi * 16 + aRow) * 128 + k16 * 32 + aK8 * 2);
                ldm_x4(a[mi], sA + SWZ(off));
            }
            #pragma unroll
            for (int fp = 0; fp < NF / 2; fp++) {
                uint32_t off = (uint32_t)((wn * (NTILE / 2) + fp * 16 + bNl) * 128 + k16 * 32 + bK8 * 2);
                uint32_t r4[4];
                ldm_x4(r4, sB + SWZ(off));
                bf[2 * fp][0] = r4[0]; bf[2 * fp][1] = r4[1];
                bf[2 * fp + 1][0] = r4[2]; bf[2 * fp + 1][1] = r4[3];
            }
            #pragma unroll
            for (int mi = 0; mi < 2; mi++)
                #pragma unroll
                for (int f = 0; f < NF; f++) mma_f16(c[mi][f], a[mi], bf[f]);
        }
        __syncthreads();
    }

    const int gID = lane >> 2, tig = lane & 3;
    #pragma unroll
    for (int mi = 0; mi < 2; mi++) {
        const int r0 = m0 + wm * 32 + mi * 16 + gID;
        #pragma unroll
        for (int f = 0; f < NF; f++) {
            const int col = n0 + wn * (NTILE / 2) + f * 8 + tig * 2;
            const float b0 = bias[col], b1 = bias[col + 1];
            float v00 = c[mi][f][0] + b0, v01 = c[mi][f][1] + b1;
            float v10 = c[mi][f][2] + b0, v11 = c[mi][f][3] + b1;
            if (relu) {
                v00 = fmaxf(v00, 0.f); v01 = fmaxf(v01, 0.f);
                v10 = fmaxf(v10, 0.f); v11 = fmaxf(v11, 0.f);
            }
            *(__half2*)(out + (size_t)r0 * N + col) = __float22half2_rn(make_float2(v00, v01));
            *(__half2*)(out + (size_t)(r0 + 8) * N + col) = __float22half2_rn(make_float2(v10, v11));
        }
    }
}

// ---------------- final GEMM: gathered A, fused qz epilogue, 2-stage ----------------
#define FSTAGE 32768
#define FQZ_OFF (2 * FSTAGE)   // 65536; W_qz tiles 16KB
__global__ void __launch_bounds__(256)
k_final(const float* __restrict__ b_out, const float* __restrict__ b_qz,
        float* __restrict__ out) {
    constexpr int NF = 8;
    extern __shared__ char smx[];
    const uint32_t sb = smem_u32(smx);
    const int tid = threadIdx.x, lane = tid & 31, wid = tid >> 5;
    const int wm = wid >> 1, wn = wid & 1;
    const int m0 = blockIdx.x * 128;
    const int NIT = 24;  // K = 1536
    const int t4 = lane >> 3;
    const int aRow = (lane & 7) + (t4 & 1) * 8;
    const int aK8  = (t4 >> 1) * 8;
    const int bNl  = (t4 >> 1) * 8 + (lane & 7);
    const int bK8  = (t4 & 1) * 8;

    auto issue = [&](int it) {
        const int kk = it * 64;
        const uint32_t sA = sb + (it & 1) * FSTAGE;
        const __half* src;
        int stride, off;
        if (kk < 960)       { src = g_past_h; stride = 960; off = kk; }
        else if (kk < 1216) { src = g_ft;     stride = 256; off = kk - 960; }
        else if (kk < 1472) { src = g_int;    stride = 256; off = kk - 1216; }
        else                { src = g_fea;    stride = 64;  off = kk - 1472; }
        #pragma unroll
        for (int v = 0; v < 4; v++) {
            int idx = tid + v * 256;
            int rr = idx >> 3, g = idx & 7;
            cp16(sA + SWZ((uint32_t)(rr * 128 + g * 16)),
                 src + (size_t)(m0 + rr) * stride + off + g * 8);
        }
        #pragma unroll
        for (int v = 0; v < 4; v++) {
            int idx = tid + v * 256;
            int rr = idx >> 3, g = idx & 7;
            cp16(sA + 16384 + SWZ((uint32_t)(rr * 128 + g * 16)),
                 g_Wout_t + (size_t)rr * 1536 + kk + g * 8);
        }
        CP_COMMIT();
    };

    // prestage W_qz (2 chunks of 64 cols, 64 rows x 128B each)
    #pragma unroll
    for (int v = 0; v < 4; v++) {
        int idx = tid + v * 256;           // 0..1023
        int ch = idx >> 9, ii = idx & 511;
        int rr = ii >> 3, g = ii & 7;
        cp16(sb + FQZ_OFF + ch * 8192 + SWZ((uint32_t)(rr * 128 + g * 16)),
             g_Wqz_t + rr * 128 + ch * 64 + g * 8);
    }
    CP_COMMIT();

    float c[2][NF][4];
    #pragma unroll
    for (int mi = 0; mi < 2; mi++)
        #pragma unroll
        for (int f = 0; f < NF; f++)
            #pragma unroll
            for (int q = 0; q < 4; q++) c[mi][f][q] = 0.f;

    issue(0);
    for (int it = 0; it < NIT; it++) {
        if (it + 1 < NIT) { issue(it + 1); CP_WAIT(1); } else { CP_WAIT(0); }
        __syncthreads();
        const uint32_t sA = sb + (it & 1) * FSTAGE;
        const uint32_t sB = sA + 16384;
        #pragma unroll
        for (int k16 = 0; k16 < 4; k16++) {
            uint32_t a[2][4], bf[NF][2];
            #pragma unroll
            for (int mi = 0; mi < 2; mi++) {
                uint32_t off = (uint32_t)((wm * 32 + mi * 16 + aRow) * 128 + k16 * 32 + aK8 * 2);
                ldm_x4(a[mi], sA + SWZ(off));
            }
            #pragma unroll
            for (int fp = 0; fp < 4; fp++) {
                uint32_t off = (uint32_t)((wn * 64 + fp * 16 + bNl) * 128 + k16 * 32 + bK8 * 2);
                uint32_t r4[4];
                ldm_x4(r4, sB + SWZ(off));
                bf[2 * fp][0] = r4[0]; bf[2 * fp][1] = r4[1];
                bf[2 * fp + 1][0] = r4[2]; bf[2 * fp + 1][1] = r4[3];
            }
            #pragma unroll
            for (int mi = 0; mi < 2; mi++)
                #pragma unroll
                for (int f = 0; f < NF; f++) mma_f16(c[mi][f], a[mi], bf[f]);
        }
        __syncthreads();
    }

    // epilogue 1: h = relu(c + b_out) -> fp16 tiles in smem (2 chunks of 64 cols)
    const int gID = lane >> 2, tig = lane & 3;
    #pragma unroll
    for (int mi = 0; mi < 2; mi++) {
        const int r0 = wm * 32 + mi * 16 + gID;
        #pragma unroll
        for (int f = 0; f < NF; f++) {
            const int col = wn * 64 + f * 8 + tig * 2;
            const float b0 = b_out[col], b1 = b_out[col + 1];
            float v00 = fmaxf(c[mi][f][0] + b0, 0.f), v01 = fmaxf(c[mi][f][1] + b1, 0.f);
            float v10 = fmaxf(c[mi][f][2] + b0, 0.f), v11 = fmaxf(c[mi][f][3] + b1, 0.f);
            const int ch = col >> 6;
            *(__half2*)(smx + ch * 16384 + SWZ((uint32_t)(r0 * 128 + (col & 63) * 2))) =
                __float22half2_rn(make_float2(v00, v01));
            *(__half2*)(smx + ch * 16384 + SWZ((uint32_t)((r0 + 8) * 128 + (col & 63) * 2))) =
                __float22half2_rn(make_float2(v10, v11));
        }
    }
    __syncthreads();

    // epilogue 2: out = h @ W_qz + b_qz (mma over smem tiles)
    float c2[2][4][4];
    #pragma unroll
    for (int mi = 0; mi < 2; mi++)
        #pragma unroll
        for (int f = 0; f < 4; f++)
            #pragma unroll
            for (int q = 0; q < 4; q++) c2[mi][f][q] = 0.f;
    #pragma unroll
    for (int ch = 0; ch < 2; ch++) {
        const uint32_t sAh = sb + ch * 16384;
        const uint32_t sBq = sb + FQZ_OFF + ch * 8192;
        #pragma unroll
        for (int k16 = 0; k16 < 4; k16++) {
            uint32_t a[2][4], bf[4][2];
            #pragma unroll
            for (int mi = 0; mi < 2; mi++) {
                uint32_t off = (uint32_t)((wm * 32 + mi * 16 + aRow) * 128 + k16 * 32 + aK8 * 2);
                ldm_x4(a[mi], sAh + SWZ(off));
            }
            #pragma unroll
            for (int fp = 0; fp < 2; fp++) {
                uint32_t off = (uint32_t)((wn * 32 + fp * 16 + bNl) * 128 + k16 * 32 + bK8 * 2);
                uint32_t r4[4];
                ldm_x4(r4, sBq + SWZ(off));
                bf[2 * fp][0] = r4[0]; bf[2 * fp][1] = r4[1];
                bf[2 * fp + 1][0] = r4[2]; bf[2 * fp + 1][1] = r4[3];
            }
            #pragma unroll
            for (int mi = 0; mi < 2; mi++)
                #pragma unroll
                for (int f = 0; f < 4; f++) mma_f16(c2[mi][f], a[mi], bf[f]);
        }
    }
    #pragma unroll
    for (int mi = 0; mi < 2; mi++) {
        const int r0 = m0 + wm * 32 + mi * 16 + gID;
        #pragma unroll
        for (int f = 0; f < 4; f++) {
            const int col = wn * 32 + f * 8 + tig * 2;
            const float b0 = b_qz[col], b1 = b_qz[col + 1];
            *(float2*)(out + (size_t)r0 * 64 + col) =
                make_float2(c2[mi][f][0] + b0, c2[mi][f][1] + b1);
            *(float2*)(out + (size_t)(r0 + 8) * 64 + col) =
                make_float2(c2[mi][f][2] + b0, c2[mi][f][3] + b1);
        }
    }
}

// ---------------- launch ----------------
extern "C" void kernel_launch(void* const* d_in, const int* in_sizes, int n_in,
                              void* d_out, int out_size) {
    const float* inputs = (const float*)d_in[0];
    const float* past   = (const float*)d_in[1];
    const float* W_in   = (const float*)d_in[2];
    const float* b_in   = (const float*)d_in[3];
    const float* W_pos  = (const float*)d_in[4];
    const float* b_pos  = (const float*)d_in[5];
    const float* W_fc2  = (const float*)d_in[6];
    const float* b_fc2  = (const float*)d_in[7];
    const float* W_fc3  = (const float*)d_in[8];
    const float* b_fc3  = (const float*)d_in[9];
    const float* W_msg  = (const float*)d_in[10];
    const float* b_msg  = (const float*)d_in[11];
    const float* W_hyp  = (const float*)d_in[12];
    const float* b_hyp  = (const float*)d_in[13];
    const float* W_line = (const float*)d_in[14];
    const float* W_out  = (const float*)d_in[15];
    const float* b_out  = (const float*)d_in[16];
    const float* W_qz   = (const float*)d_in[17];
    const float* b_qz   = (const float*)d_in[18];
    float* out = (float*)d_out;

    void *pFt, *pAgg, *pHag, *pInt, *pHyp, *pFea, *pZero;
    void *pWmsg, *pWhyp, *pWlin;
    cudaGetSymbolAddress(&pFt,  g_ft);
    cudaGetSymbolAddress(&pAgg, g_agg);
    cudaGetSymbolAddress(&pHag, g_hag);
    cudaGetSymbolAddress(&pInt, g_int);
    cudaGetSymbolAddress(&pHyp, g_hyp);
    cudaGetSymbolAddress(&pFea, g_fea);
    cudaGetSymbolAddress(&pZero, g_zero64);
    cudaGetSymbolAddress(&pWmsg, g_Wmsg_t);
    cudaGetSymbolAddress(&pWhyp, g_Whyp_t);
    cudaGetSymbolAddress(&pWlin, g_Wlin_t);

    cudaFuncSetAttribute(k_mma<128>, cudaFuncAttributeMaxDynamicSharedMemorySize, 3 * 32768);
    cudaFuncSetAttribute(k_mma<64>,  cudaFuncAttributeMaxDynamicSharedMemorySize, 3 * 24576);
    cudaFuncSetAttribute(k_final,    cudaFuncAttributeMaxDynamicSharedMemorySize, 81920);

    pk12<<<12, 256>>>(W_in, b_in, W_pos, b_pos, W_fc2);
    pk3<<<49, 256>>>(W_fc3, b_fc3, b_fc2);
    prep<<<NB_ALL, 256>>>(W_msg, W_hyp, W_out, W_line, W_qz, past);
    scene_kernel<<<B_SZ, 256>>>(inputs);

    // inter = relu([ft|agg] @ W_msg + b_msg)
    k_mma<128><<<dim3(2, MTILES), 256, 3 * 32768>>>(
        (const __half*)pFt, (const __half*)pAgg, (const __half*)pWmsg, b_msg,
        (__half*)pInt, 512, 256, 256, 1);
    // hyp = relu([ft|hag] @ W_hyp + b_hyp)
    k_mma<128><<<dim3(2, MTILES), 256, 3 * 32768>>>(
        (const __half*)pFt, (const __half*)pHag, (const __half*)pWhyp, b_hyp,
        (__half*)pHyp, 512, 256, 256, 1);
    // feat = hyp @ W_line
    k_mma<64><<<dim3(1, MTILES), 256, 3 * 24576>>>(
        (const __half*)pHyp, (const __half*)pHyp, (const __half*)pWlin, (const float*)pZero,
        (__half*)pFea, 256, 256, 64, 0);
    // h = relu([past|ft|inter|feat] @ W_out + b_out); out = h @ W_qz + b_qz
    k_final<<<MTILES, 256, 81920>>>(b_out, b_qz, out);
}

// round 7
// speedup vs baseline: 3.5077x; 1.0371x over previous
#include <cuda_runtime.h>
#include <cuda_fp16.h>
#include <math.h>
#include <stdint.h>

// Problem constants
#define B_SZ   4096
#define N_AG   11
#define BN_ROWS (B_SZ * N_AG)      // 45056
#define MTILES  (BN_ROWS / 128)    // 352

// ---------------- device scratch ----------------
__device__ float g_Weff[48 * 256];
__device__ float g_ceffp[12 * 256];
__device__ float g_G[48 * 256];
__device__ float g_cb[11 * 256];
__device__ float g_zero64[64];     // zero bias (never written)

// fp16 activations
__device__ __half g_past_h[(size_t)BN_ROWS * 960];
__device__ __half g_ft [(size_t)BN_ROWS * 256];
__device__ __half g_agg[(size_t)BN_ROWS * 256];
__device__ __half g_hag[(size_t)BN_ROWS * 256];
__device__ __half g_int[(size_t)BN_ROWS * 256];
__device__ __half g_hyp[(size_t)BN_ROWS * 256];
__device__ __half g_fea[(size_t)BN_ROWS * 64];
// fp16 transposed weights [n][K]
__device__ __half g_Wmsg_t[256 * 512];
__device__ __half g_Whyp_t[256 * 512];
__device__ __half g_Wout_t[128 * 1536];
__device__ __half g_Wlin_t[64 * 256];
__device__ __half g_Wqz_t [64 * 128];

// ---------------- helpers ----------------
#define SWZ(o) ((o) ^ (((o) >> 3) & 0x70))
__device__ __forceinline__ uint32_t smem_u32(const void* p) {
    uint32_t a;
    asm("{ .reg .u64 t; cvta.to.shared.u64 t, %1; cvt.u32.u64 %0, t; }" : "=r"(a) : "l"(p));
    return a;
}
__device__ __forceinline__ void ldm_x4(uint32_t* r, uint32_t addr) {
    asm volatile("ldmatrix.sync.aligned.m8n8.x4.shared.b16 {%0,%1,%2,%3}, [%4];"
                 : "=r"(r[0]), "=r"(r[1]), "=r"(r[2]), "=r"(r[3]) : "r"(addr));
}
__device__ __forceinline__ void mma_f16(float* c, const uint32_t* a, const uint32_t* b) {
    asm("mma.sync.aligned.m16n8k16.row.col.f32.f16.f16.f32 "
        "{%0,%1,%2,%3},{%4,%5,%6,%7},{%8,%9},{%0,%1,%2,%3};"
        : "+f"(c[0]), "+f"(c[1]), "+f"(c[2]), "+f"(c[3])
        : "r"(a[0]), "r"(a[1]), "r"(a[2]), "r"(a[3]), "r"(b[0]), "r"(b[1]));
}
__device__ __forceinline__ void cp16(uint32_t dst, const void* src) {
    asm volatile("cp.async.cg.shared.global [%0], [%1], 16;"
                 :: "r"(dst), "l"(__cvta_generic_to_global(src)) : "memory");
}
#define CP_COMMIT() asm volatile("cp.async.commit_group;" ::: "memory")
#define CP_WAIT(n)  asm volatile("cp.async.wait_group %0;" :: "n"(n) : "memory")

// ---------------- pk12: folded front-end (12 blocks) ----------------
__global__ void __launch_bounds__(256)
pk12(const float* __restrict__ W_in, const float* __restrict__ b_in,
     const float* __restrict__ W_pos, const float* __restrict__ b_pos,
     const float* __restrict__ W_fc2) {
    __shared__ float pe[256];
    __shared__ float sM4[4 * 256];
    __shared__ float sbt[256];
    const int t = blockIdx.x, d = threadIdx.x;
    {
        int k = d, i2 = k & ~1;
        float div = expf(-logf(10000.0f) * (float)i2 / 256.0f);
        float arg = (float)t * div;
        pe[k] = (k & 1) ? cosf(arg) : sinf(arg);
    }
    __syncthreads();
    float m[4] = {0.f, 0.f, 0.f, 0.f};
    float bb = 0.f;
    for (int k = 0; k < 256; k++) {
        float w = W_pos[k * 256 + d];
        #pragma unroll
        for (int r = 0; r < 4; r++) m[r] += W_in[r * 256 + k] * w;
        bb += b_in[k] * w;
    }
    float acc = bb + b_pos[d];
    for (int k = 0; k < 256; k++)
        acc += pe[k] * W_pos[(256 + k) * 256 + d];
    #pragma unroll
    for (int r = 0; r < 4; r++) sM4[r * 256 + d] = m[r];
    sbt[d] = acc;
    __syncthreads();
    float accW[4] = {0.f, 0.f, 0.f, 0.f};
    float accC = 0.f;
    #pragma unroll 4
    for (int mm = 0; mm < 256; mm++) {
        float w = W_fc2[(size_t)((t << 8) + mm) * 256 + d];
        #pragma unroll
        for (int r = 0; r < 4; r++) accW[r] += sM4[r * 256 + mm] * w;
        accC += sbt[mm] * w;
    }
    #pragma unroll
    for (int r = 0; r < 4; r++) g_Weff[(t * 4 + r) * 256 + d] = accW[r];
    g_ceffp[t * 256 + d] = accC;
}

// ---------------- pk3: fold fc3 (49 blocks) ----------------
__global__ void __launch_bounds__(256)
pk3(const float* __restrict__ W_fc3, const float* __restrict__ b_fc3,
    const float* __restrict__ b_fc2) {
    const int d = threadIdx.x;
    if (blockIdx.x < 48) {
        const int i = blockIdx.x;
        float a0 = 0.f, a1 = 0.f, a2 = 0.f, a3 = 0.f;
        #pragma unroll 4
        for (int m = 0; m < 256; m += 4) {
            a0 += g_Weff[i * 256 + m + 0] * W_fc3[(m + 0) * 256 + d];
            a1 += g_Weff[i * 256 + m + 1] * W_fc3[(m + 1) * 256 + d];
            a2 += g_Weff[i * 256 + m + 2] * W_fc3[(m + 2) * 256 + d];
            a3 += g_Weff[i * 256 + m + 3] * W_fc3[(m + 3) * 256 + d];
        }
        g_G[i * 256 + d] = (a0 + a1) + (a2 + a3);
    } else {
        __shared__ float ce[256];
        float s = b_fc2[d];
        #pragma unroll
        for (int t = 0; t < 12; t++) s += g_ceffp[t * 256 + d];
        ce[d] = s;
        __syncthreads();
        float a0 = b_fc3[d], a1 = 0.f, a2 = 0.f, a3 = 0.f;
        #pragma unroll 4
        for (int m = 0; m < 256; m += 4) {
            a0 += ce[m + 0] * W_fc3[(m + 0) * 256 + d];
            a1 += ce[m + 1] * W_fc3[(m + 1) * 256 + d];
            a2 += ce[m + 2] * W_fc3[(m + 2) * 256 + d];
            a3 += ce[m + 3] * W_fc3[(m + 3) * 256 + d];
        }
        float acc = (a0 + a1) + (a2 + a3);
        #pragma unroll
        for (int n = 0; n < 11; n++) g_cb[n * 256 + d] = acc + W_fc3[(256 + n) * 256 + d];
    }
}

// ---------------- prep: weight transposes (fp16) + past conversion ----------------
#define NB_W 512
#define NB_ALL 4096
__global__ void __launch_bounds__(256)
prep(const float* __restrict__ W_msg, const float* __restrict__ W_hyp,
     const float* __restrict__ W_out, const float* __restrict__ W_line,
     const float* __restrict__ W_qz,  const float* __restrict__ past) {
    if (blockIdx.x < NB_W) {
        const int stride = NB_W * 256;
        for (int idx = blockIdx.x * 256 + threadIdx.x; idx < 483328; idx += stride) {
            if (idx < 131072) {
                int n = idx >> 9, k = idx & 511;
                g_Wmsg_t[idx] = __float2half(W_msg[(size_t)k * 256 + n]);
            } else if (idx < 262144) {
                int i = idx - 131072;
                int n = i >> 9, k = i & 511;
                g_Whyp_t[i] = __float2half(W_hyp[(size_t)k * 256 + n]);
            } else if (idx < 458752) {
                int i = idx - 262144;
                int n = i / 1536, k = i % 1536;
                g_Wout_t[i] = __float2half(W_out[(size_t)k * 128 + n]);
            } else if (idx < 475136) {
                int i = idx - 458752;
                int n = i >> 8, k = i & 255;
                g_Wlin_t[i] = __float2half(W_line[(size_t)k * 64 + n]);
            } else {
                int i = idx - 475136;
                int n = i >> 7, k = i & 127;
                g_Wqz_t[i] = __float2half(W_qz[(size_t)k * 64 + n]);
            }
        }
    } else {
        const size_t total = (size_t)BN_ROWS * 960 / 4;
        const size_t stride = (size_t)(NB_ALL - NB_W) * 256;
        for (size_t i = (size_t)(blockIdx.x - NB_W) * 256 + threadIdx.x; i < total; i += stride) {
            float4 f = ((const float4*)past)[i];
            __half2 h0 = __float22half2_rn(make_float2(f.x, f.y));
            __half2 h1 = __float22half2_rn(make_float2(f.z, f.w));
            ((__half2*)g_past_h)[2 * i]     = h0;
            ((__half2*)g_past_h)[2 * i + 1] = h1;
        }
    }
}

// ---------------- per-scene kernel (LDS-slim) ----------------
__global__ void __launch_bounds__(256)
scene_kernel(const float* __restrict__ inputs) {
    __shared__ float inT[48 * 12];     // transposed, padded: inT[k][n]
    __shared__ float ft[11 * 256];     // fp32 for dots
    __shared__ float dot_s[121];
    __shared__ float corr_s[121];
    __shared__ float2 attn2_s[121];    // (.x = attn, .y = arow)
    __shared__ float nrm[11];
    __shared__ float thr_s;

    const int b = blockIdx.x, tid = threadIdx.x;
    const float* ip = inputs + (size_t)b * 11 * 48;
    // transpose-stage inputs: i = n*48 + k -> inT[k*12 + n]
    if (tid < 48) inT[tid * 12 + 11] = 0.f;
    for (int i = tid; i < 528; i += 256) {
        int n = i / 48, k = i - n * 48;
        inT[k * 12 + n] = ip[i];
    }
    __syncthreads();

    // ftraj: acc[n] = cb[n][tid] + sum_k inT[k][n] * G[k][tid]
    float acc[12];
    #pragma unroll
    for (int n = 0; n < 11; n++) acc[n] = g_cb[n * 256 + tid];
    acc[11] = 0.f;
    for (int k = 0; k < 48; k++) {
        float g = g_G[k * 256 + tid];
        float4 v0 = *(const float4*)&inT[k * 12 + 0];
        float4 v1 = *(const float4*)&inT[k * 12 + 4];
        float4 v2 = *(const float4*)&inT[k * 12 + 8];
        acc[0] += v0.x * g; acc[1] += v0.y * g; acc[2] += v0.z * g; acc[3] += v0.w * g;
        acc[4] += v1.x * g; acc[5] += v1.y * g; acc[6] += v1.z * g; acc[7] += v1.w * g;
        acc[8] += v2.x * g; acc[9] += v2.y * g; acc[10] += v2.w * 0.f + v2.z * g;
    }
    const size_t rowbase = (size_t)b * 11;
    #pragma unroll
    for (int n = 0; n < 11; n++) {
        ft[n * 256 + tid] = acc[n];
        g_ft[(rowbase + n) * 256 + tid] = __float2half(acc[n]);
    }
    __syncthreads();

    // pairwise dots
    const int warp = tid >> 5, lane = tid & 31;
    for (int p = warp; p < 121; p += 8) {
        int n = p / 11, m = p % 11;
        if (m < n) continue;
        float s = 0.f;
        #pragma unroll
        for (int i = 0; i < 8; i++)
            s += ft[n * 256 + lane + 32 * i] * ft[m * 256 + lane + 32 * i];
        #pragma unroll
        for (int o = 16; o > 0; o >>= 1) s += __shfl_down_sync(0xffffffffu, s, o);
        if (lane == 0) { dot_s[n * 11 + m] = s; dot_s[m * 11 + n] = s; }
    }
    __syncthreads();
    if (tid < 11) nrm[tid] = sqrtf(dot_s[tid * 11 + tid]);
    __syncthreads();
    if (tid < 121) {
        int n = tid / 11, m = tid % 11;
        corr_s[tid] = dot_s[tid] / (nrm[n] * nrm[m]);
    }
    __syncthreads();
    if (tid == 0) {
        float a = corr_s[0];
        for (int i = 1; i < 121; i++) a = fminf(a, corr_s[i]);
        float thr;
        if (a < 0.4f)                  thr = 0.4f;
        else if (a > 0.4f && a < 0.6f) thr = a + 0.1f;
        else                           thr = a + 0.03f;
        thr_s = thr;
    }
    __syncthreads();
    if (tid < 11) {
        const int n = tid;
        const float thr = thr_s;
        float rs = 0.f;
        #pragma unroll
        for (int m = 0; m < 11; m++) rs += (corr_s[n * 11 + m] >= thr) ? 1.0f : 0.0f;
        const float inv = 1.0f / fmaxf(rs, 1.0f);
        const float sc = 0.0625f;
        float mx = -1e30f;
        #pragma unroll
        for (int m = 0; m < 11; m++) mx = fmaxf(mx, dot_s[n * 11 + m] * sc);
        float e[11], se = 0.f;
        #pragma unroll
        for (int m = 0; m < 11; m++) { e[m] = expf(dot_s[n * 11 + m] * sc - mx); se += e[m]; }
        const float is = 1.0f / se;
        #pragma unroll
        for (int m = 0; m < 11; m++) {
            float ar = (corr_s[n * 11 + m] >= thr) ? inv : 0.0f;
            attn2_s[n * 11 + m] = make_float2(e[m] * is, ar);
        }
    }
    __syncthreads();
    // mixing from registers: f(m) = acc[m]
    float acc_a[11], acc_h[11];
    #pragma unroll
    for (int n = 0; n < 11; n++) { acc_a[n] = 0.f; acc_h[n] = 0.f; }
    #pragma unroll
    for (int m = 0; m < 11; m++) {
        const float f = acc[m];
        #pragma unroll
        for (int n = 0; n < 11; n++) {
            float2 w = attn2_s[n * 11 + m];
            acc_a[n] += w.x * f;
            acc_h[n] += w.y * f;
        }
    }
    #pragma unroll
    for (int n = 0; n < 11; n++) {
        g_agg[(rowbase + n) * 256 + tid] = __float2half(acc_a[n]);
        g_hag[(rowbase + n) * 256 + tid] = __float2half(acc_h[n]);
    }
}

// ---------------- fp16 tensor-core GEMM, 3-stage cp.async pipeline ----------------
template<int NTILE>
__global__ void __launch_bounds__(256)
k_mma(const __half* __restrict__ A1, const __half* __restrict__ A2,
      const __half* __restrict__ Bt, const float* __restrict__ bias,
      __half* __restrict__ out, int K, int K1, int N, int relu) {
    constexpr int NF = NTILE / 16;
    constexpr int STAGE = 16384 + NTILE * 128;
    extern __shared__ char smx[];
    const uint32_t sb = smem_u32(smx);
    const int tid = threadIdx.x, lane = tid & 31, wid = tid >> 5;
    const int wm = wid >> 1, wn = wid & 1;
    const int m0 = blockIdx.y * 128, n0 = blockIdx.x * NTILE;
    const int NIT = K / 64;
    const int K2 = K - K1;
    const int t4 = lane >> 3;
    const int aRow = (lane & 7) + (t4 & 1) * 8;
    const int aK8  = (t4 >> 1) * 8;
    const int bNl  = (t4 >> 1) * 8 + (lane & 7);
    const int bK8  = (t4 & 1) * 8;

    auto issue = [&](int it) {
        const int kk = it * 64;
        const uint32_t sA = sb + (it % 3) * STAGE;
        #pragma unroll
        for (int v = 0; v < 4; v++) {
            int idx = tid + v * 256;
            int rr = idx >> 3, g = idx & 7;
            const __half* s = (kk < K1)
                ? A1 + (size_t)(m0 + rr) * K1 + kk + g * 8
                : A2 + (size_t)(m0 + rr) * K2 + (kk - K1) + g * 8;
            cp16(sA + SWZ((uint32_t)(rr * 128 + g * 16)), s);
        }
        #pragma unroll
        for (int v = 0; v < NTILE / 32; v++) {
            int idx = tid + v * 256;
            int rr = idx >> 3, g = idx & 7;
            cp16(sA + 16384 + SWZ((uint32_t)(rr * 128 + g * 16)),
                 Bt + (size_t)(n0 + rr) * K + kk + g * 8);
        }
        CP_COMMIT();
    };

    float c[2][NF][4];
    #pragma unroll
    for (int mi = 0; mi < 2; mi++)
        #pragma unroll
        for (int f = 0; f < NF; f++)
            #pragma unroll
            for (int q = 0; q < 4; q++) c[mi][f][q] = 0.f;

    issue(0);
    if (NIT > 1) issue(1);
    for (int it = 0; it < NIT; it++) {
        if (it + 2 < NIT)      { issue(it + 2); CP_WAIT(2); }
        else if (it + 1 < NIT) { CP_WAIT(1); }
        else                   { CP_WAIT(0); }
        __syncthreads();
        const uint32_t sA = sb + (it % 3) * STAGE;
        const uint32_t sB = sA + 16384;
        #pragma unroll
        for (int k16 = 0; k16 < 4; k16++) {
            uint32_t a[2][4], bf[NF][2];
            #pragma unroll
            for (int mi = 0; mi < 2; mi++) {
                uint32_t off = (uint32_t)((wm * 32 + mi * 16 + aRow) * 128 + k16 * 32 + aK8 * 2);
                ldm_x4(a[mi], sA + SWZ(off));
            }
            #pragma unroll
            for (int fp = 0; fp < NF / 2; fp++) {
                uint32_t off = (uint32_t)((wn * (NTILE / 2) + fp * 16 + bNl) * 128 + k16 * 32 + bK8 * 2);
                uint32_t r4[4];
                ldm_x4(r4, sB + SWZ(off));
                bf[2 * fp][0] = r4[0]; bf[2 * fp][1] = r4[1];
                bf[2 * fp + 1][0] = r4[2]; bf[2 * fp + 1][1] = r4[3];
            }
            #pragma unroll
            for (int mi = 0; mi < 2; mi++)
                #pragma unroll
                for (int f = 0; f < NF; f++) mma_f16(c[mi][f], a[mi], bf[f]);
        }
        __syncthreads();
    }

    const int gID = lane >> 2, tig = lane & 3;
    #pragma unroll
    for (int mi = 0; mi < 2; mi++) {
        const int r0 = m0 + wm * 32 + mi * 16 + gID;
        #pragma unroll
        for (int f = 0; f < NF; f++) {
            const int col = n0 + wn * (NTILE / 2) + f * 8 + tig * 2;
            const float b0 = bias[col], b1 = bias[col + 1];
            float v00 = c[mi][f][0] + b0, v01 = c[mi][f][1] + b1;
            float v10 = c[mi][f][2] + b0, v11 = c[mi][f][3] + b1;
            if (relu) {
                v00 = fmaxf(v00, 0.f); v01 = fmaxf(v01, 0.f);
                v10 = fmaxf(v10, 0.f); v11 = fmaxf(v11, 0.f);
            }
            *(__half2*)(out + (size_t)r0 * N + col) = __float22half2_rn(make_float2(v00, v01));
            *(__half2*)(out + (size_t)(r0 + 8) * N + col) = __float22half2_rn(make_float2(v10, v11));
        }
    }
}

// ---------------- final GEMM: gathered A, fused qz epilogue, 3-stage ----------------
#define FSTAGE 32768
#define FQZ_OFF (3 * FSTAGE)   // 98304; W_qz tiles 16KB => 114688 total
__global__ void __launch_bounds__(256)
k_final(const float* __restrict__ b_out, const float* __restrict__ b_qz,
        float* __restrict__ out) {
    constexpr int NF = 8;
    extern __shared__ char smx[];
    const uint32_t sb = smem_u32(smx);
    const int tid = threadIdx.x, lane = tid & 31, wid = tid >> 5;
    const int wm = wid >> 1, wn = wid & 1;
    const int m0 = blockIdx.x * 128;
    const int NIT = 24;  // K = 1536
    const int t4 = lane >> 3;
    const int aRow = (lane & 7) + (t4 & 1) * 8;
    const int aK8  = (t4 >> 1) * 8;
    const int bNl  = (t4 >> 1) * 8 + (lane & 7);
    const int bK8  = (t4 & 1) * 8;

    auto issue = [&](int it) {
        const int kk = it * 64;
        const uint32_t sA = sb + (it % 3) * FSTAGE;
        const __half* src;
        int stride, off;
        if (kk < 960)       { src = g_past_h; stride = 960; off = kk; }
        else if (kk < 1216) { src = g_ft;     stride = 256; off = kk - 960; }
        else if (kk < 1472) { src = g_int;    stride = 256; off = kk - 1216; }
        else                { src = g_fea;    stride = 64;  off = kk - 1472; }
        #pragma unroll
        for (int v = 0; v < 4; v++) {
            int idx = tid + v * 256;
            int rr = idx >> 3, g = idx & 7;
            cp16(sA + SWZ((uint32_t)(rr * 128 + g * 16)),
                 src + (size_t)(m0 + rr) * stride + off + g * 8);
        }
        #pragma unroll
        for (int v = 0; v < 4; v++) {
            int idx = tid + v * 256;
            int rr = idx >> 3, g = idx & 7;
            cp16(sA + 16384 + SWZ((uint32_t)(rr * 128 + g * 16)),
                 g_Wout_t + (size_t)rr * 1536 + kk + g * 8);
        }
        CP_COMMIT();
    };

    // prestage W_qz (2 chunks of 64 cols)
    #pragma unroll
    for (int v = 0; v < 4; v++) {
        int idx = tid + v * 256;           // 0..1023
        int ch = idx >> 9, ii = idx & 511;
        int rr = ii >> 3, g = ii & 7;
        cp16(sb + FQZ_OFF + ch * 8192 + SWZ((uint32_t)(rr * 128 + g * 16)),
             g_Wqz_t + rr * 128 + ch * 64 + g * 8);
    }
    CP_COMMIT();

    float c[2][NF][4];
    #pragma unroll
    for (int mi = 0; mi < 2; mi++)
        #pragma unroll
        for (int f = 0; f < NF; f++)
            #pragma unroll
            for (int q = 0; q < 4; q++) c[mi][f][q] = 0.f;

    issue(0);
    issue(1);
    for (int it = 0; it < NIT; it++) {
        if (it + 2 < NIT)      { issue(it + 2); CP_WAIT(2); }
        else if (it + 1 < NIT) { CP_WAIT(1); }
        else                   { CP_WAIT(0); }
        __syncthreads();
        const uint32_t sA = sb + (it % 3) * FSTAGE;
        const uint32_t sB = sA + 16384;
        #pragma unroll
        for (int k16 = 0; k16 < 4; k16++) {
            uint32_t a[2][4], bf[NF][2];
            #pragma unroll
            for (int mi = 0; mi < 2; mi++) {
                uint32_t off = (uint32_t)((wm * 32 + mi * 16 + aRow) * 128 + k16 * 32 + aK8 * 2);
                ldm_x4(a[mi], sA + SWZ(off));
            }
            #pragma unroll
            for (int fp = 0; fp < 4; fp++) {
                uint32_t off = (uint32_t)((wn * 64 + fp * 16 + bNl) * 128 + k16 * 32 + bK8 * 2);
                uint32_t r4[4];
                ldm_x4(r4, sB + SWZ(off));
                bf[2 * fp][0] = r4[0]; bf[2 * fp][1] = r4[1];
                bf[2 * fp + 1][0] = r4[2]; bf[2 * fp + 1][1] = r4[3];
            }
            #pragma unroll
            for (int mi = 0; mi < 2; mi++)
                #pragma unroll
                for (int f = 0; f < NF; f++) mma_f16(c[mi][f], a[mi], bf[f]);
        }
        __syncthreads();
    }

    // epilogue 1: h = relu(c + b_out) -> fp16 tiles in smem (reuse stage 0/1 space)
    const int gID = lane >> 2, tig = lane & 3;
    #pragma unroll
    for (int mi = 0; mi < 2; mi++) {
        const int r0 = wm * 32 + mi * 16 + gID;
        #pragma unroll
        for (int f = 0; f < NF; f++) {
            const int col = wn * 64 + f * 8 + tig * 2;
            const float b0 = b_out[col], b1 = b_out[col + 1];
            float v00 = fmaxf(c[mi][f][0] + b0, 0.f), v01 = fmaxf(c[mi][f][1] + b1, 0.f);
            float v10 = fmaxf(c[mi][f][2] + b0, 0.f), v11 = fmaxf(c[mi][f][3] + b1, 0.f);
            const int ch = col >> 6;
            *(__half2*)(smx + ch * 16384 + SWZ((uint32_t)(r0 * 128 + (col & 63) * 2))) =
                __float22half2_rn(make_float2(v00, v01));
            *(__half2*)(smx + ch * 16384 + SWZ((uint32_t)((r0 + 8) * 128 + (col & 63) * 2))) =
                __float22half2_rn(make_float2(v10, v11));
        }
    }
    __syncthreads();

    // epilogue 2: out = h @ W_qz + b_qz
    float c2[2][4][4];
    #pragma unroll
    for (int mi = 0; mi < 2; mi++)
        #pragma unroll
        for (int f = 0; f < 4; f++)
            #pragma unroll
            for (int q = 0; q < 4; q++) c2[mi][f][q] = 0.f;
    #pragma unroll
    for (int ch = 0; ch < 2; ch++) {
        const uint32_t sAh = sb + ch * 16384;
        const uint32_t sBq = sb + FQZ_OFF + ch * 8192;
        #pragma unroll
        for (int k16 = 0; k16 < 4; k16++) {
            uint32_t a[2][4], bf[4][2];
            #pragma unroll
            for (int mi = 0; mi < 2; mi++) {
                uint32_t off = (uint32_t)((wm * 32 + mi * 16 + aRow) * 128 + k16 * 32 + aK8 * 2);
                ldm_x4(a[mi], sAh + SWZ(off));
            }
            #pragma unroll
            for (int fp = 0; fp < 2; fp++) {
                uint32_t off = (uint32_t)((wn * 32 + fp * 16 + bNl) * 128 + k16 * 32 + bK8 * 2);
                uint32_t r4[4];
                ldm_x4(r4, sBq + SWZ(off));
                bf[2 * fp][0] = r4[0]; bf[2 * fp][1] = r4[1];
                bf[2 * fp + 1][0] = r4[2]; bf[2 * fp + 1][1] = r4[3];
            }
            #pragma unroll
            for (int mi = 0; mi < 2; mi++)
                #pragma unroll
                for (int f = 0; f < 4; f++) mma_f16(c2[mi][f], a[mi], bf[f]);
        }
    }
    #pragma unroll
    for (int mi = 0; mi < 2; mi++) {
        const int r0 = m0 + wm * 32 + mi * 16 + gID;
        #pragma unroll
        for (int f = 0; f < 4; f++) {
            const int col = wn * 32 + f * 8 + tig * 2;
            const float b0 = b_qz[col], b1 = b_qz[col + 1];
            *(float2*)(out + (size_t)r0 * 64 + col) =
                make_float2(c2[mi][f][0] + b0, c2[mi][f][1] + b1);
            *(float2*)(out + (size_t)(r0 + 8) * 64 + col) =
                make_float2(c2[mi][f][2] + b0, c2[mi][f][3] + b1);
        }
    }
}

// ---------------- launch ----------------
extern "C" void kernel_launch(void* const* d_in, const int* in_sizes, int n_in,
                              void* d_out, int out_size) {
    const float* inputs = (const float*)d_in[0];
    const float* past   = (const float*)d_in[1];
    const float* W_in   = (const float*)d_in[2];
    const float* b_in   = (const float*)d_in[3];
    const float* W_pos  = (const float*)d_in[4];
    const float* b_pos  = (const float*)d_in[5];
    const float* W_fc2  = (const float*)d_in[6];
    const float* b_fc2  = (const float*)d_in[7];
    const float* W_fc3  = (const float*)d_in[8];
    const float* b_fc3  = (const float*)d_in[9];
    const float* W_msg  = (const float*)d_in[10];
    const float* b_msg  = (const float*)d_in[11];
    const float* W_hyp  = (const float*)d_in[12];
    const float* b_hyp  = (const float*)d_in[13];
    const float* W_line = (const float*)d_in[14];
    const float* W_out  = (const float*)d_in[15];
    const float* b_out  = (const float*)d_in[16];
    const float* W_qz   = (const float*)d_in[17];
    const float* b_qz   = (const float*)d_in[18];
    float* out = (float*)d_out;

    void *pFt, *pAgg, *pHag, *pInt, *pHyp, *pFea, *pZero;
    void *pWmsg, *pWhyp, *pWlin;
    cudaGetSymbolAddress(&pFt,  g_ft);
    cudaGetSymbolAddress(&pAgg, g_agg);
    cudaGetSymbolAddress(&pHag, g_hag);
    cudaGetSymbolAddress(&pInt, g_int);
    cudaGetSymbolAddress(&pHyp, g_hyp);
    cudaGetSymbolAddress(&pFea, g_fea);
    cudaGetSymbolAddress(&pZero, g_zero64);
    cudaGetSymbolAddress(&pWmsg, g_Wmsg_t);
    cudaGetSymbolAddress(&pWhyp, g_Whyp_t);
    cudaGetSymbolAddress(&pWlin, g_Wlin_t);

    cudaFuncSetAttribute(k_mma<128>, cudaFuncAttributeMaxDynamicSharedMemorySize, 3 * 32768);
    cudaFuncSetAttribute(k_mma<64>,  cudaFuncAttributeMaxDynamicSharedMemorySize, 3 * 24576);
    cudaFuncSetAttribute(k_final,    cudaFuncAttributeMaxDynamicSharedMemorySize, 114688);

    pk12<<<12, 256>>>(W_in, b_in, W_pos, b_pos, W_fc2);
    pk3<<<49, 256>>>(W_fc3, b_fc3, b_fc2);
    prep<<<NB_ALL, 256>>>(W_msg, W_hyp, W_out, W_line, W_qz, past);
    scene_kernel<<<B_SZ, 256>>>(inputs);

    // inter = relu([ft|agg] @ W_msg + b_msg)
    k_mma<128><<<dim3(2, MTILES), 256, 3 * 32768>>>(
        (const __half*)pFt, (const __half*)pAgg, (const __half*)pWmsg, b_msg,
        (__half*)pInt, 512, 256, 256, 1);
    // hyp = relu([ft|hag] @ W_hyp + b_hyp)
    k_mma<128><<<dim3(2, MTILES), 256, 3 * 32768>>>(
        (const __half*)pFt, (const __half*)pHag, (const __half*)pWhyp, b_hyp,
        (__half*)pHyp, 512, 256, 256, 1);
    // feat = hyp @ W_line
    k_mma<64><<<dim3(1, MTILES), 256, 3 * 24576>>>(
        (const __half*)pHyp, (const __half*)pHyp, (const __half*)pWlin, (const float*)pZero,
        (__half*)pFea, 256, 256, 64, 0);
    // h = relu([past|ft|inter|feat] @ W_out + b_out); out = h @ W_qz + b_qz
    k_final<<<MTILES, 256, 114688>>>(b_out, b_qz, out);
}